// round 1
// baseline (speedup 1.0000x reference)
#include <cuda_runtime.h>
#include <cstdint>
#include <cstddef>

#define T_TOK 8192
#define DIM   1024
#define FDIM  2752
#define NEXP  8

// ---------------- scratch (static device globals; allocation-free) ----------
__device__ int   g_cnt[NEXP];
__device__ int   g_tok[NEXP * T_TOK];
__device__ int   g_slot[T_TOK * 2];
__device__ float g_cw[T_TOK * 2];
__device__ float g_H [(size_t)NEXP * T_TOK * FDIM];   // routed hidden
__device__ float g_Hs[(size_t)T_TOK * FDIM];          // shared-expert hidden
__device__ float g_Yr[(size_t)NEXP * T_TOK * DIM];    // routed out
__device__ float g_Ys[(size_t)T_TOK * DIM];           // shared-expert out

// ---------------- helpers ---------------------------------------------------
__device__ __forceinline__ float tf32r(float x) {
    asm("cvt.rna.tf32.f32 %0, %0;" : "+f"(x));
    return x;
}

__device__ __forceinline__ void mma_tf32(float* c, const uint32_t* a, const uint32_t* b) {
    asm volatile(
        "mma.sync.aligned.m16n8k8.row.col.f32.tf32.tf32.f32 "
        "{%0,%1,%2,%3}, {%4,%5,%6,%7}, {%8,%9}, {%0,%1,%2,%3};\n"
        : "+f"(c[0]), "+f"(c[1]), "+f"(c[2]), "+f"(c[3])
        : "r"(a[0]), "r"(a[1]), "r"(a[2]), "r"(a[3]),
          "r"(b[0]), "r"(b[1]));
}

// ---------------- router -----------------------------------------------------
__global__ void zero_kernel() {
    if (threadIdx.x < NEXP) g_cnt[threadIdx.x] = 0;
}

__global__ void router_kernel(const float* __restrict__ x,
                              const float* __restrict__ rw,
                              const float* __restrict__ rb) {
    int wid = threadIdx.x >> 5, lane = threadIdx.x & 31;
    int t = blockIdx.x * 8 + wid;
    if (t >= T_TOK) return;
    const float* xr = x + (size_t)t * DIM;
    float lg[NEXP] = {0.f,0.f,0.f,0.f,0.f,0.f,0.f,0.f};
    for (int j = lane; j < DIM; j += 32) {
        float xv = xr[j];
        const float* w = rw + (size_t)j * NEXP;
        #pragma unroll
        for (int e = 0; e < NEXP; e++) lg[e] += xv * w[e];
    }
    #pragma unroll
    for (int e = 0; e < NEXP; e++) {
        #pragma unroll
        for (int o = 16; o > 0; o >>= 1)
            lg[e] += __shfl_xor_sync(0xffffffffu, lg[e], o);
    }
    if (lane == 0) {
        float p[NEXP];
        #pragma unroll
        for (int e = 0; e < NEXP; e++) lg[e] += rb[e];
        float m = lg[0];
        #pragma unroll
        for (int e = 1; e < NEXP; e++) m = fmaxf(m, lg[e]);
        float s = 0.f;
        #pragma unroll
        for (int e = 0; e < NEXP; e++) { p[e] = __expf(lg[e] - m); s += p[e]; }
        #pragma unroll
        for (int e = 0; e < NEXP; e++) p[e] /= s;
        int e0 = 0;
        #pragma unroll
        for (int e = 1; e < NEXP; e++) if (p[e] > p[e0]) e0 = e;
        int e1 = (e0 == 0) ? 1 : 0;
        #pragma unroll
        for (int e = 0; e < NEXP; e++) if (e != e0 && p[e] > p[e1]) e1 = e;
        float den = p[e0] + p[e1] + 1e-20f;
        float w0 = p[e0] / den, w1 = p[e1] / den;
        int pos0 = atomicAdd(&g_cnt[e0], 1);
        g_tok[e0 * T_TOK + pos0] = t;
        g_slot[2 * t]     = e0 * T_TOK + pos0;
        g_cw[2 * t]       = w0;
        int pos1 = atomicAdd(&g_cnt[e1], 1);
        g_tok[e1 * T_TOK + pos1] = t;
        g_slot[2 * t + 1] = e1 * T_TOK + pos1;
        g_cw[2 * t + 1]   = w1;
    }
}

// ---------------- GEMM tiling constants -------------------------------------
#define BM 128
#define BN 64
#define BK 16
#define ASTR (BK + 4)   // 20 floats: conflict-free for A-frag reads
#define BSTR (BN + 8)   // 72 floats: conflict-free for B-frag reads

// ---------------- stage 1: H = silu(X@G) * (X@U)  (gathered rows) -----------
// mode = 0: routed (expert = blockIdx.z, gather via g_tok, cnt via g_cnt)
// mode = 1: shared (identity rows, cnt = T_TOK, write g_Hs)
__global__ __launch_bounds__(256) void ffn1_kernel(
    const float* __restrict__ x,
    const float* __restrict__ gw_base,
    const float* __restrict__ uw_base,
    int mode)
{
    int e   = blockIdx.z;
    int cnt = mode ? T_TOK : g_cnt[e];
    int m0  = blockIdx.x * BM;
    if (m0 >= cnt) return;
    int n0  = blockIdx.y * BN;

    const float* gw = gw_base + (size_t)e * DIM * FDIM;
    const float* uw = uw_base + (size_t)e * DIM * FDIM;
    const int*  tok = mode ? nullptr : (g_tok + e * T_TOK);
    float* H = mode ? g_Hs : (g_H + (size_t)e * T_TOK * FDIM);

    __shared__ float As[BM * ASTR];
    __shared__ float Bg[BK * BSTR];
    __shared__ float Bu[BK * BSTR];

    int tid  = threadIdx.x;
    int lane = tid & 31, wid = tid >> 5;
    int wm = wid & 1, wn = wid >> 1;

    // A-load plan: 2 x float4 per thread
    size_t aoff[2]; bool aval[2]; int ar[2], ak[2];
    #pragma unroll
    for (int i = 0; i < 2; i++) {
        int idx  = tid + i * 256;
        int r    = idx >> 2;
        int kseg = (idx & 3) * 4;
        int grow = m0 + r;
        bool v   = grow < cnt;
        int tk   = v ? (tok ? tok[grow] : grow) : 0;
        aoff[i] = (size_t)tk * DIM + kseg;
        aval[i] = v; ar[i] = r; ak[i] = kseg;
    }
    int brr = tid >> 4;          // 0..15
    int bcc = (tid & 15) * 4;    // 0..60

    float cg[4][2][4] = {};
    float cu[4][2][4] = {};

    for (int k0 = 0; k0 < DIM; k0 += BK) {
        float4 av[2];
        #pragma unroll
        for (int i = 0; i < 2; i++)
            av[i] = aval[i] ? *(const float4*)(x + aoff[i] + k0)
                            : make_float4(0.f, 0.f, 0.f, 0.f);
        float4 gv = *(const float4*)(gw + (size_t)(k0 + brr) * FDIM + n0 + bcc);
        float4 uv = *(const float4*)(uw + (size_t)(k0 + brr) * FDIM + n0 + bcc);

        __syncthreads();
        #pragma unroll
        for (int i = 0; i < 2; i++) {
            float* p = As + ar[i] * ASTR + ak[i];
            p[0] = tf32r(av[i].x); p[1] = tf32r(av[i].y);
            p[2] = tf32r(av[i].z); p[3] = tf32r(av[i].w);
        }
        {
            float* p = Bg + brr * BSTR + bcc;
            p[0] = tf32r(gv.x); p[1] = tf32r(gv.y);
            p[2] = tf32r(gv.z); p[3] = tf32r(gv.w);
            float* q = Bu + brr * BSTR + bcc;
            q[0] = tf32r(uv.x); q[1] = tf32r(uv.y);
            q[2] = tf32r(uv.z); q[3] = tf32r(uv.w);
        }
        __syncthreads();

        #pragma unroll
        for (int ks = 0; ks < BK; ks += 8) {
            uint32_t af[4][4];
            #pragma unroll
            for (int mi = 0; mi < 4; mi++) {
                int r = wm * 64 + mi * 16 + (lane >> 2);
                int c = ks + (lane & 3);
                af[mi][0] = __float_as_uint(As[r * ASTR + c]);
                af[mi][1] = __float_as_uint(As[(r + 8) * ASTR + c]);
                af[mi][2] = __float_as_uint(As[r * ASTR + c + 4]);
                af[mi][3] = __float_as_uint(As[(r + 8) * ASTR + c + 4]);
            }
            uint32_t bgf[2][2], buf2[2][2];
            #pragma unroll
            for (int ni = 0; ni < 2; ni++) {
                int cc = wn * 16 + ni * 8 + (lane >> 2);
                int kk = ks + (lane & 3);
                bgf[ni][0]  = __float_as_uint(Bg[kk * BSTR + cc]);
                bgf[ni][1]  = __float_as_uint(Bg[(kk + 4) * BSTR + cc]);
                buf2[ni][0] = __float_as_uint(Bu[kk * BSTR + cc]);
                buf2[ni][1] = __float_as_uint(Bu[(kk + 4) * BSTR + cc]);
            }
            #pragma unroll
            for (int mi = 0; mi < 4; mi++) {
                #pragma unroll
                for (int ni = 0; ni < 2; ni++) {
                    mma_tf32(cg[mi][ni], af[mi], bgf[ni]);
                    mma_tf32(cu[mi][ni], af[mi], buf2[ni]);
                }
            }
        }
    }

    // epilogue: SwiGLU
    #pragma unroll
    for (int mi = 0; mi < 4; mi++) {
        #pragma unroll
        for (int ni = 0; ni < 2; ni++) {
            int rbase = m0 + wm * 64 + mi * 16 + (lane >> 2);
            int cbase = n0 + wn * 16 + ni * 8 + (lane & 3) * 2;
            #pragma unroll
            for (int h = 0; h < 2; h++) {
                int row = rbase + h * 8;
                if (row < cnt) {
                    float g0 = cg[mi][ni][h * 2 + 0], g1 = cg[mi][ni][h * 2 + 1];
                    float u0 = cu[mi][ni][h * 2 + 0], u1 = cu[mi][ni][h * 2 + 1];
                    float h0 = g0 / (1.f + __expf(-g0)) * u0;
                    float h1 = g1 / (1.f + __expf(-g1)) * u1;
                    H[(size_t)row * FDIM + cbase]     = h0;
                    H[(size_t)row * FDIM + cbase + 1] = h1;
                }
            }
        }
    }
}

// ---------------- stage 2: Y = H @ down -------------------------------------
__global__ __launch_bounds__(256) void ffn2_kernel(
    const float* __restrict__ dw_base,
    int mode)
{
    int e   = blockIdx.z;
    int cnt = mode ? T_TOK : g_cnt[e];
    int m0  = blockIdx.x * BM;
    if (m0 >= cnt) return;
    int n0  = blockIdx.y * BN;

    const float* A  = mode ? g_Hs : (g_H + (size_t)e * T_TOK * FDIM);
    const float* dw = dw_base + (size_t)e * FDIM * DIM;
    float* Y = mode ? g_Ys : (g_Yr + (size_t)e * T_TOK * DIM);

    __shared__ float As[BM * ASTR];
    __shared__ float Bs[BK * BSTR];

    int tid  = threadIdx.x;
    int lane = tid & 31, wid = tid >> 5;
    int wm = wid & 1, wn = wid >> 1;

    size_t aoff[2]; bool aval[2]; int ar[2], ak[2];
    #pragma unroll
    for (int i = 0; i < 2; i++) {
        int idx  = tid + i * 256;
        int r    = idx >> 2;
        int kseg = (idx & 3) * 4;
        int grow = m0 + r;
        bool v   = grow < cnt;
        aoff[i] = (size_t)(v ? grow : 0) * FDIM + kseg;
        aval[i] = v; ar[i] = r; ak[i] = kseg;
    }
    int brr = tid >> 4;
    int bcc = (tid & 15) * 4;

    float cc_[4][2][4] = {};

    for (int k0 = 0; k0 < FDIM; k0 += BK) {
        float4 av[2];
        #pragma unroll
        for (int i = 0; i < 2; i++)
            av[i] = aval[i] ? *(const float4*)(A + aoff[i] + k0)
                            : make_float4(0.f, 0.f, 0.f, 0.f);
        float4 bv = *(const float4*)(dw + (size_t)(k0 + brr) * DIM + n0 + bcc);

        __syncthreads();
        #pragma unroll
        for (int i = 0; i < 2; i++) {
            float* p = As + ar[i] * ASTR + ak[i];
            p[0] = tf32r(av[i].x); p[1] = tf32r(av[i].y);
            p[2] = tf32r(av[i].z); p[3] = tf32r(av[i].w);
        }
        {
            float* p = Bs + brr * BSTR + bcc;
            p[0] = tf32r(bv.x); p[1] = tf32r(bv.y);
            p[2] = tf32r(bv.z); p[3] = tf32r(bv.w);
        }
        __syncthreads();

        #pragma unroll
        for (int ks = 0; ks < BK; ks += 8) {
            uint32_t af[4][4];
            #pragma unroll
            for (int mi = 0; mi < 4; mi++) {
                int r = wm * 64 + mi * 16 + (lane >> 2);
                int c = ks + (lane & 3);
                af[mi][0] = __float_as_uint(As[r * ASTR + c]);
                af[mi][1] = __float_as_uint(As[(r + 8) * ASTR + c]);
                af[mi][2] = __float_as_uint(As[r * ASTR + c + 4]);
                af[mi][3] = __float_as_uint(As[(r + 8) * ASTR + c + 4]);
            }
            uint32_t bf[2][2];
            #pragma unroll
            for (int ni = 0; ni < 2; ni++) {
                int ccc = wn * 16 + ni * 8 + (lane >> 2);
                int kk  = ks + (lane & 3);
                bf[ni][0] = __float_as_uint(Bs[kk * BSTR + ccc]);
                bf[ni][1] = __float_as_uint(Bs[(kk + 4) * BSTR + ccc]);
            }
            #pragma unroll
            for (int mi = 0; mi < 4; mi++)
                #pragma unroll
                for (int ni = 0; ni < 2; ni++)
                    mma_tf32(cc_[mi][ni], af[mi], bf[ni]);
        }
    }

    #pragma unroll
    for (int mi = 0; mi < 4; mi++) {
        #pragma unroll
        for (int ni = 0; ni < 2; ni++) {
            int rbase = m0 + wm * 64 + mi * 16 + (lane >> 2);
            int cbase = n0 + wn * 16 + ni * 8 + (lane & 3) * 2;
            #pragma unroll
            for (int h = 0; h < 2; h++) {
                int row = rbase + h * 8;
                if (row < cnt) {
                    Y[(size_t)row * DIM + cbase]     = cc_[mi][ni][h * 2 + 0];
                    Y[(size_t)row * DIM + cbase + 1] = cc_[mi][ni][h * 2 + 1];
                }
            }
        }
    }
}

// ---------------- combine ----------------------------------------------------
__global__ void combine_kernel(float* __restrict__ out) {
    int i  = blockIdx.x * blockDim.x + threadIdx.x;   // over T*D/4
    int t  = i / (DIM / 4);
    int dv = (i % (DIM / 4)) * 4;
    float w0 = g_cw[2 * t], w1 = g_cw[2 * t + 1];
    size_t s0 = (size_t)g_slot[2 * t] * DIM + dv;
    size_t s1 = (size_t)g_slot[2 * t + 1] * DIM + dv;
    float4 a = *(const float4*)(g_Yr + s0);
    float4 b = *(const float4*)(g_Yr + s1);
    float4 c = *(const float4*)(g_Ys + (size_t)t * DIM + dv);
    float4 o;
    o.x = w0 * a.x + w1 * b.x + c.x;
    o.y = w0 * a.y + w1 * b.y + c.y;
    o.z = w0 * a.z + w1 * b.z + c.z;
    o.w = w0 * a.w + w1 * b.w + c.w;
    *(float4*)(out + (size_t)t * DIM + dv) = o;
}

// ---------------- launch ------------------------------------------------------
extern "C" void kernel_launch(void* const* d_in, const int* in_sizes, int n_in,
                              void* d_out, int out_size) {
    const float* x   = (const float*)d_in[0];
    const float* rw  = (const float*)d_in[1];
    const float* rb  = (const float*)d_in[2];
    const float* gw  = (const float*)d_in[3];
    const float* uw  = (const float*)d_in[4];
    const float* dw  = (const float*)d_in[5];
    const float* sgw = (const float*)d_in[6];
    const float* suw = (const float*)d_in[7];
    const float* sdw = (const float*)d_in[8];
    float* out = (float*)d_out;

    zero_kernel<<<1, 32>>>();
    router_kernel<<<T_TOK / 8, 256>>>(x, rw, rb);

    dim3 g1(T_TOK / BM, FDIM / BN, NEXP);   // 64 x 43 x 8
    ffn1_kernel<<<g1, 256>>>(x, gw, uw, /*mode=*/0);
    dim3 g1s(T_TOK / BM, FDIM / BN, 1);
    ffn1_kernel<<<g1s, 256>>>(x, sgw, suw, /*mode=*/1);

    dim3 g2(T_TOK / BM, DIM / BN, NEXP);    // 64 x 16 x 8
    ffn2_kernel<<<g2, 256>>>(dw, /*mode=*/0);
    dim3 g2s(T_TOK / BM, DIM / BN, 1);
    ffn2_kernel<<<g2s, 256>>>(sdw, /*mode=*/1);

    combine_kernel<<<(T_TOK * (DIM / 4)) / 256, 256>>>(out);
}

// round 3
// speedup vs baseline: 1.2887x; 1.2887x over previous
#include <cuda_runtime.h>
#include <cstdint>
#include <cstddef>

#define T_TOK 8192
#define DIM   1024
#define FDIM  2752
#define NEXP  8

#define BM 128
#define BN 64
#define BK 16
#define ASTR 20
#define BSTR 72
#define STAGES 4
#define A_BYTES (BM * ASTR * 4)            // 10240
#define B_BYTES (BK * BSTR * 4)            // 4608
#define ST1_BYTES (A_BYTES + 2 * B_BYTES)  // 19456
#define ST2_BYTES (A_BYTES + B_BYTES)      // 14848
#define SMEM1 (STAGES * ST1_BYTES)         // 77824
#define SMEM2 (STAGES * ST2_BYTES)         // 59392

// ---------------- scratch ----------------------------------------------------
__device__ int   g_cnt[NEXP];
__device__ int   g_tok[NEXP * T_TOK];
__device__ int   g_slot[T_TOK * 2];
__device__ float g_cw[T_TOK * 2];
__device__ float g_xr [(size_t)T_TOK * DIM];
__device__ float g_gwR[(size_t)NEXP * DIM * FDIM];
__device__ float g_uwR[(size_t)NEXP * DIM * FDIM];
__device__ float g_dwR[(size_t)NEXP * FDIM * DIM];
__device__ float g_sgwR[(size_t)DIM * FDIM];
__device__ float g_suwR[(size_t)DIM * FDIM];
__device__ float g_sdwR[(size_t)FDIM * DIM];
__device__ float g_H  [(size_t)NEXP * T_TOK * FDIM];
__device__ float g_Hs [(size_t)T_TOK * FDIM];
__device__ float g_Yr [(size_t)NEXP * T_TOK * DIM];
__device__ float g_Ys [(size_t)T_TOK * DIM];

// ---------------- helpers ----------------------------------------------------
__device__ __forceinline__ float tf32r(float x) {
    asm("cvt.rna.tf32.f32 %0, %0;" : "+f"(x));
    return x;
}
__device__ __forceinline__ uint32_t smem_u32(const void* p) {
    uint32_t a;
    asm("{ .reg .u64 t; cvta.to.shared.u64 t, %1; cvt.u32.u64 %0, t; }" : "=r"(a) : "l"(p));
    return a;
}
__device__ __forceinline__ void cpa16(uint32_t dst, const void* src, uint32_t nbytes) {
    asm volatile("cp.async.cg.shared.global [%0], [%1], 16, %2;"
                 :: "r"(dst), "l"(src), "r"(nbytes) : "memory");
}
#define CP_COMMIT() asm volatile("cp.async.commit_group;" ::: "memory")
#define CP_WAIT2()  asm volatile("cp.async.wait_group 2;" ::: "memory")

__device__ __forceinline__ void mma_tf32(float* c, const uint32_t* a, const uint32_t* b) {
    asm volatile(
        "mma.sync.aligned.m16n8k8.row.col.f32.tf32.tf32.f32 "
        "{%0,%1,%2,%3}, {%4,%5,%6,%7}, {%8,%9}, {%0,%1,%2,%3};\n"
        : "+f"(c[0]), "+f"(c[1]), "+f"(c[2]), "+f"(c[3])
        : "r"(a[0]), "r"(a[1]), "r"(a[2]), "r"(a[3]),
          "r"(b[0]), "r"(b[1]));
}

// ---------------- pre-processing ---------------------------------------------
__global__ void roundcopy_kernel(const float* __restrict__ src, float* __restrict__ dst) {
    size_t i = (size_t)blockIdx.x * 256 + threadIdx.x;
    float4 v = ((const float4*)src)[i];
    v.x = tf32r(v.x); v.y = tf32r(v.y); v.z = tf32r(v.z); v.w = tf32r(v.w);
    ((float4*)dst)[i] = v;
}

// ---------------- router -----------------------------------------------------
__global__ void zero_kernel() {
    if (threadIdx.x < NEXP) g_cnt[threadIdx.x] = 0;
}

__global__ void router_kernel(const float* __restrict__ x,
                              const float* __restrict__ rw,
                              const float* __restrict__ rb) {
    int wid = threadIdx.x >> 5, lane = threadIdx.x & 31;
    int t = blockIdx.x * 8 + wid;
    if (t >= T_TOK) return;
    const float* xrow = x + (size_t)t * DIM;
    float lg[NEXP] = {0.f,0.f,0.f,0.f,0.f,0.f,0.f,0.f};
    for (int j = lane; j < DIM; j += 32) {
        float xv = xrow[j];
        const float* w = rw + (size_t)j * NEXP;
        #pragma unroll
        for (int e = 0; e < NEXP; e++) lg[e] += xv * w[e];
    }
    #pragma unroll
    for (int e = 0; e < NEXP; e++)
        #pragma unroll
        for (int o = 16; o > 0; o >>= 1)
            lg[e] += __shfl_xor_sync(0xffffffffu, lg[e], o);
    if (lane == 0) {
        float p[NEXP];
        #pragma unroll
        for (int e = 0; e < NEXP; e++) lg[e] += rb[e];
        float m = lg[0];
        #pragma unroll
        for (int e = 1; e < NEXP; e++) m = fmaxf(m, lg[e]);
        float s = 0.f;
        #pragma unroll
        for (int e = 0; e < NEXP; e++) { p[e] = __expf(lg[e] - m); s += p[e]; }
        #pragma unroll
        for (int e = 0; e < NEXP; e++) p[e] /= s;
        int e0 = 0;
        #pragma unroll
        for (int e = 1; e < NEXP; e++) if (p[e] > p[e0]) e0 = e;
        int e1 = (e0 == 0) ? 1 : 0;
        #pragma unroll
        for (int e = 0; e < NEXP; e++) if (e != e0 && p[e] > p[e1]) e1 = e;
        float den = p[e0] + p[e1] + 1e-20f;
        int pos0 = atomicAdd(&g_cnt[e0], 1);
        g_tok[e0 * T_TOK + pos0] = t;
        g_slot[2 * t]     = e0 * T_TOK + pos0;
        g_cw[2 * t]       = p[e0] / den;
        int pos1 = atomicAdd(&g_cnt[e1], 1);
        g_tok[e1 * T_TOK + pos1] = t;
        g_slot[2 * t + 1] = e1 * T_TOK + pos1;
        g_cw[2 * t + 1]   = p[e1] / den;
    }
}

// ---------------- stage 1: H = silu(X@G) * (X@U), cp.async pipeline ---------
__global__ void __launch_bounds__(256, 2) ffn1_cp(
    const float* __restrict__ xr,
    const float* __restrict__ gw_base,
    const float* __restrict__ uw_base,
    int mode)
{
    int e   = blockIdx.z;
    int cnt = mode ? T_TOK : g_cnt[e];
    int m0  = blockIdx.x * BM;
    if (m0 >= cnt) return;
    int n0  = blockIdx.y * BN;

    const int* tok = mode ? nullptr : (g_tok + e * T_TOK);
    float* H = mode ? g_Hs : (g_H + (size_t)e * T_TOK * FDIM);
    const float* gw = gw_base + (size_t)e * DIM * FDIM;
    const float* uw = uw_base + (size_t)e * DIM * FDIM;

    extern __shared__ char smem[];
    uint32_t sb = smem_u32(smem);
    int tid  = threadIdx.x;
    int lane = tid & 31, wid = tid >> 5;
    int wm = wid & 1, wn = wid >> 1;

    // A: 2 x 16B per thread; B: 1 x 16B per thread per matrix
    const char* aSrc[2]; uint32_t aZ[2], aDst[2];
    #pragma unroll
    for (int j = 0; j < 2; j++) {
        int idx = tid + j * 256;
        int row = idx >> 2, seg = idx & 3;
        aDst[j] = (uint32_t)(row * (ASTR * 4) + seg * 16);
        int grow = m0 + row;
        bool v = grow < cnt;
        int tk = v ? (tok ? tok[grow] : grow) : 0;
        aSrc[j] = (const char*)(xr + (size_t)tk * DIM) + seg * 16;
        aZ[j] = v ? 16u : 0u;
    }
    int brow = tid >> 4, bseg = tid & 15;
    uint32_t bDst = (uint32_t)(brow * (BSTR * 4) + bseg * 16);
    const char* gSrc = (const char*)(gw + (size_t)brow * FDIM + n0) + bseg * 16;
    const char* uSrc = (const char*)(uw + (size_t)brow * FDIM + n0) + bseg * 16;
    const size_t bStep = (size_t)BK * FDIM * 4;

    float cg[4][2][4] = {};
    float cu[4][2][4] = {};

    auto issue = [&](int k) {
        uint32_t base = sb + (uint32_t)(k & 3) * ST1_BYTES;
        cpa16(base + aDst[0], aSrc[0] + (size_t)k * 64, aZ[0]);
        cpa16(base + aDst[1], aSrc[1] + (size_t)k * 64, aZ[1]);
        cpa16(base + A_BYTES + bDst,           gSrc + (size_t)k * bStep, 16u);
        cpa16(base + A_BYTES + B_BYTES + bDst, uSrc + (size_t)k * bStep, 16u);
        CP_COMMIT();
    };

    issue(0); issue(1); issue(2);
    const int KIT = DIM / BK;  // 64
    for (int k = 0; k < KIT; k++) {
        CP_WAIT2();
        __syncthreads();
        const float* As = (const float*)(smem + (k & 3) * ST1_BYTES);
        const float* Bg = (const float*)(smem + (k & 3) * ST1_BYTES + A_BYTES);
        const float* Bu = (const float*)(smem + (k & 3) * ST1_BYTES + A_BYTES + B_BYTES);

        #pragma unroll
        for (int ks = 0; ks < BK; ks += 8) {
            uint32_t af[4][4];
            #pragma unroll
            for (int mi = 0; mi < 4; mi++) {
                int r = wm * 64 + mi * 16 + (lane >> 2);
                int c = ks + (lane & 3);
                af[mi][0] = __float_as_uint(As[r * ASTR + c]);
                af[mi][1] = __float_as_uint(As[(r + 8) * ASTR + c]);
                af[mi][2] = __float_as_uint(As[r * ASTR + c + 4]);
                af[mi][3] = __float_as_uint(As[(r + 8) * ASTR + c + 4]);
            }
            uint32_t bgf[2][2], buf2[2][2];
            #pragma unroll
            for (int ni = 0; ni < 2; ni++) {
                int cc = wn * 16 + ni * 8 + (lane >> 2);
                int kk = ks + (lane & 3);
                bgf[ni][0]  = __float_as_uint(Bg[kk * BSTR + cc]);
                bgf[ni][1]  = __float_as_uint(Bg[(kk + 4) * BSTR + cc]);
                buf2[ni][0] = __float_as_uint(Bu[kk * BSTR + cc]);
                buf2[ni][1] = __float_as_uint(Bu[(kk + 4) * BSTR + cc]);
            }
            #pragma unroll
            for (int mi = 0; mi < 4; mi++) {
                #pragma unroll
                for (int ni = 0; ni < 2; ni++) {
                    mma_tf32(cg[mi][ni], af[mi], bgf[ni]);
                    mma_tf32(cu[mi][ni], af[mi], buf2[ni]);
                }
            }
        }
        if (k + 3 < KIT) issue(k + 3); else CP_COMMIT();
    }

    // epilogue: SwiGLU (+ tf32 round for the next GEMM's cp.async path)
    #pragma unroll
    for (int mi = 0; mi < 4; mi++) {
        #pragma unroll
        for (int ni = 0; ni < 2; ni++) {
            int rbase = m0 + wm * 64 + mi * 16 + (lane >> 2);
            int cbase = n0 + wn * 16 + ni * 8 + (lane & 3) * 2;
            #pragma unroll
            for (int h = 0; h < 2; h++) {
                int row = rbase + h * 8;
                if (row < cnt) {
                    float g0 = cg[mi][ni][h * 2 + 0], g1 = cg[mi][ni][h * 2 + 1];
                    float u0 = cu[mi][ni][h * 2 + 0], u1 = cu[mi][ni][h * 2 + 1];
                    float h0 = tf32r(g0 / (1.f + __expf(-g0)) * u0);
                    float h1 = tf32r(g1 / (1.f + __expf(-g1)) * u1);
                    H[(size_t)row * FDIM + cbase]     = h0;
                    H[(size_t)row * FDIM + cbase + 1] = h1;
                }
            }
        }
    }
}

// ---------------- stage 2: Y = H @ down, cp.async pipeline -------------------
__global__ void __launch_bounds__(256, 2) ffn2_cp(
    const float* __restrict__ dw_base,
    int mode)
{
    int e   = blockIdx.z;
    int cnt = mode ? T_TOK : g_cnt[e];
    int m0  = blockIdx.x * BM;
    if (m0 >= cnt) return;
    int n0  = blockIdx.y * BN;

    const float* A  = mode ? g_Hs : (g_H + (size_t)e * T_TOK * FDIM);
    const float* dw = dw_base + (size_t)e * FDIM * DIM;
    float* Y = mode ? g_Ys : (g_Yr + (size_t)e * T_TOK * DIM);

    extern __shared__ char smem[];
    uint32_t sb = smem_u32(smem);
    int tid  = threadIdx.x;
    int lane = tid & 31, wid = tid >> 5;
    int wm = wid & 1, wn = wid >> 1;

    const char* aSrc[2]; uint32_t aZ[2], aDst[2];
    #pragma unroll
    for (int j = 0; j < 2; j++) {
        int idx = tid + j * 256;
        int row = idx >> 2, seg = idx & 3;
        aDst[j] = (uint32_t)(row * (ASTR * 4) + seg * 16);
        int grow = m0 + row;
        bool v = grow < cnt;
        aSrc[j] = (const char*)(A + (size_t)(v ? grow : 0) * FDIM) + seg * 16;
        aZ[j] = v ? 16u : 0u;
    }
    int brow = tid >> 4, bseg = tid & 15;
    uint32_t bDst = (uint32_t)(brow * (BSTR * 4) + bseg * 16);
    const char* bSrc = (const char*)(dw + (size_t)brow * DIM + n0) + bseg * 16;
    const size_t bStep = (size_t)BK * DIM * 4;

    float cc_[4][2][4] = {};

    auto issue = [&](int k) {
        uint32_t base = sb + (uint32_t)(k & 3) * ST2_BYTES;
        cpa16(base + aDst[0], aSrc[0] + (size_t)k * 64, aZ[0]);
        cpa16(base + aDst[1], aSrc[1] + (size_t)k * 64, aZ[1]);
        cpa16(base + A_BYTES + bDst, bSrc + (size_t)k * bStep, 16u);
        CP_COMMIT();
    };

    issue(0); issue(1); issue(2);
    const int KIT = FDIM / BK;  // 172
    for (int k = 0; k < KIT; k++) {
        CP_WAIT2();
        __syncthreads();
        const float* As = (const float*)(smem + (k & 3) * ST2_BYTES);
        const float* Bs = (const float*)(smem + (k & 3) * ST2_BYTES + A_BYTES);

        #pragma unroll
        for (int ks = 0; ks < BK; ks += 8) {
            uint32_t af[4][4];
            #pragma unroll
            for (int mi = 0; mi < 4; mi++) {
                int r = wm * 64 + mi * 16 + (lane >> 2);
                int c = ks + (lane & 3);
                af[mi][0] = __float_as_uint(As[r * ASTR + c]);
                af[mi][1] = __float_as_uint(As[(r + 8) * ASTR + c]);
                af[mi][2] = __float_as_uint(As[r * ASTR + c + 4]);
                af[mi][3] = __float_as_uint(As[(r + 8) * ASTR + c + 4]);
            }
            uint32_t bf[2][2];
            #pragma unroll
            for (int ni = 0; ni < 2; ni++) {
                int ccc = wn * 16 + ni * 8 + (lane >> 2);
                int kk  = ks + (lane & 3);
                bf[ni][0] = __float_as_uint(Bs[kk * BSTR + ccc]);
                bf[ni][1] = __float_as_uint(Bs[(kk + 4) * BSTR + ccc]);
            }
            #pragma unroll
            for (int mi = 0; mi < 4; mi++)
                #pragma unroll
                for (int ni = 0; ni < 2; ni++)
                    mma_tf32(cc_[mi][ni], af[mi], bf[ni]);
        }
        if (k + 3 < KIT) issue(k + 3); else CP_COMMIT();
    }

    #pragma unroll
    for (int mi = 0; mi < 4; mi++) {
        #pragma unroll
        for (int ni = 0; ni < 2; ni++) {
            int rbase = m0 + wm * 64 + mi * 16 + (lane >> 2);
            int cbase = n0 + wn * 16 + ni * 8 + (lane & 3) * 2;
            #pragma unroll
            for (int h = 0; h < 2; h++) {
                int row = rbase + h * 8;
                if (row < cnt) {
                    Y[(size_t)row * DIM + cbase]     = cc_[mi][ni][h * 2 + 0];
                    Y[(size_t)row * DIM + cbase + 1] = cc_[mi][ni][h * 2 + 1];
                }
            }
        }
    }
}

// ---------------- combine ----------------------------------------------------
__global__ void combine_kernel(float* __restrict__ out) {
    int i  = blockIdx.x * blockDim.x + threadIdx.x;
    int t  = i / (DIM / 4);
    int dv = (i % (DIM / 4)) * 4;
    float w0 = g_cw[2 * t], w1 = g_cw[2 * t + 1];
    size_t s0 = (size_t)g_slot[2 * t] * DIM + dv;
    size_t s1 = (size_t)g_slot[2 * t + 1] * DIM + dv;
    float4 a = *(const float4*)(g_Yr + s0);
    float4 b = *(const float4*)(g_Yr + s1);
    float4 c = *(const float4*)(g_Ys + (size_t)t * DIM + dv);
    float4 o;
    o.x = w0 * a.x + w1 * b.x + c.x;
    o.y = w0 * a.y + w1 * b.y + c.y;
    o.z = w0 * a.z + w1 * b.z + c.z;
    o.w = w0 * a.w + w1 * b.w + c.w;
    *(float4*)(out + (size_t)t * DIM + dv) = o;
}

// ---------------- launch ------------------------------------------------------
extern "C" void kernel_launch(void* const* d_in, const int* in_sizes, int n_in,
                              void* d_out, int out_size) {
    const float* x   = (const float*)d_in[0];
    const float* rw  = (const float*)d_in[1];
    const float* rb  = (const float*)d_in[2];
    const float* gw  = (const float*)d_in[3];
    const float* uw  = (const float*)d_in[4];
    const float* dw  = (const float*)d_in[5];
    const float* sgw = (const float*)d_in[6];
    const float* suw = (const float*)d_in[7];
    const float* sdw = (const float*)d_in[8];
    float* out = (float*)d_out;

    cudaFuncSetAttribute(ffn1_cp, cudaFuncAttributeMaxDynamicSharedMemorySize, SMEM1);
    cudaFuncSetAttribute(ffn2_cp, cudaFuncAttributeMaxDynamicSharedMemorySize, SMEM2);

    float *xr, *gwR, *uwR, *dwR, *sgwR, *suwR, *sdwR;
    cudaGetSymbolAddress((void**)&xr,   g_xr);
    cudaGetSymbolAddress((void**)&gwR,  g_gwR);
    cudaGetSymbolAddress((void**)&uwR,  g_uwR);
    cudaGetSymbolAddress((void**)&dwR,  g_dwR);
    cudaGetSymbolAddress((void**)&sgwR, g_sgwR);
    cudaGetSymbolAddress((void**)&suwR, g_suwR);
    cudaGetSymbolAddress((void**)&sdwR, g_sdwR);

    // tf32-round all GEMM operands (one elementwise pass each)
    roundcopy_kernel<<<(T_TOK * DIM) / 1024, 256>>>(x, xr);
    roundcopy_kernel<<<(int)(((size_t)NEXP * DIM * FDIM) / 1024), 256>>>(gw, gwR);
    roundcopy_kernel<<<(int)(((size_t)NEXP * DIM * FDIM) / 1024), 256>>>(uw, uwR);
    roundcopy_kernel<<<(int)(((size_t)NEXP * FDIM * DIM) / 1024), 256>>>(dw, dwR);
    roundcopy_kernel<<<(DIM * FDIM) / 1024, 256>>>(sgw, sgwR);
    roundcopy_kernel<<<(DIM * FDIM) / 1024, 256>>>(suw, suwR);
    roundcopy_kernel<<<(FDIM * DIM) / 1024, 256>>>(sdw, sdwR);

    zero_kernel<<<1, 32>>>();
    router_kernel<<<T_TOK / 8, 256>>>(x, rw, rb);

    dim3 g1(T_TOK / BM, FDIM / BN, NEXP);   // 64 x 43 x 8
    ffn1_cp<<<g1, 256, SMEM1>>>(xr, gwR, uwR, 0);
    dim3 g1s(T_TOK / BM, FDIM / BN, 1);
    ffn1_cp<<<g1s, 256, SMEM1>>>(xr, sgwR, suwR, 1);

    dim3 g2(T_TOK / BM, DIM / BN, NEXP);    // 64 x 16 x 8
    ffn2_cp<<<g2, 256, SMEM2>>>(dwR, 0);
    dim3 g2s(T_TOK / BM, DIM / BN, 1);
    ffn2_cp<<<g2s, 256, SMEM2>>>(sdwR, 1);

    combine_kernel<<<(T_TOK * (DIM / 4)) / 256, 256>>>(out);
}

// round 4
// speedup vs baseline: 1.4333x; 1.1122x over previous
#include <cuda_runtime.h>
#include <cstdint>
#include <cstddef>

#define T_TOK 8192
#define DIM   1024
#define FDIM  2752
#define NEXP  8

#define BM 128
#define BN 64
#define BK 16
#define ASTR 20
#define BSTR 72
#define STAGES 4
#define A_BYTES (BM * ASTR * 4)            // 10240
#define B_BYTES (BK * BSTR * 4)            // 4608
#define ST1_BYTES (A_BYTES + 2 * B_BYTES)  // 19456
#define SMEM1 (STAGES * ST1_BYTES)         // 77824

// ffn2: BN2=128
#define BN2 128
#define BSTR2 136
#define B2_BYTES (BK * BSTR2 * 4)          // 8704
#define ST2_BYTES (A_BYTES + B2_BYTES)     // 18944
#define SMEM2 (STAGES * ST2_BYTES)         // 75776

// ---------------- scratch ----------------------------------------------------
__device__ int   g_cnt[NEXP];
__device__ int   g_tok[NEXP * T_TOK];
__device__ int   g_slot[T_TOK * 2];
__device__ float g_cw[T_TOK * 2];
__device__ float g_xr [(size_t)T_TOK * DIM];
__device__ float g_gwR[(size_t)NEXP * DIM * FDIM];
__device__ float g_uwR[(size_t)NEXP * DIM * FDIM];
__device__ float g_dwR[(size_t)NEXP * FDIM * DIM];
__device__ float g_sgwR[(size_t)DIM * FDIM];
__device__ float g_suwR[(size_t)DIM * FDIM];
__device__ float g_sdwR[(size_t)FDIM * DIM];
__device__ float g_H  [(size_t)NEXP * T_TOK * FDIM];
__device__ float g_Hs [(size_t)T_TOK * FDIM];
__device__ float g_Yr [(size_t)NEXP * T_TOK * DIM];
__device__ float g_Ys [(size_t)T_TOK * DIM];

// ---------------- helpers ----------------------------------------------------
__device__ __forceinline__ float tf32r(float x) {
    asm("cvt.rna.tf32.f32 %0, %0;" : "+f"(x));
    return x;
}
__device__ __forceinline__ uint32_t smem_u32(const void* p) {
    uint32_t a;
    asm("{ .reg .u64 t; cvta.to.shared.u64 t, %1; cvt.u32.u64 %0, t; }" : "=r"(a) : "l"(p));
    return a;
}
__device__ __forceinline__ void cpa16(uint32_t dst, const void* src, uint32_t nbytes) {
    asm volatile("cp.async.cg.shared.global [%0], [%1], 16, %2;"
                 :: "r"(dst), "l"(src), "r"(nbytes) : "memory");
}
#define CP_COMMIT() asm volatile("cp.async.commit_group;" ::: "memory")
#define CP_WAIT2()  asm volatile("cp.async.wait_group 2;" ::: "memory")

__device__ __forceinline__ void mma_tf32(float* c, const uint32_t* a, const uint32_t* b) {
    asm volatile(
        "mma.sync.aligned.m16n8k8.row.col.f32.tf32.tf32.f32 "
        "{%0,%1,%2,%3}, {%4,%5,%6,%7}, {%8,%9}, {%0,%1,%2,%3};\n"
        : "+f"(c[0]), "+f"(c[1]), "+f"(c[2]), "+f"(c[3])
        : "r"(a[0]), "r"(a[1]), "r"(a[2]), "r"(a[3]),
          "r"(b[0]), "r"(b[1]));
}

// ---------------- pre-processing ---------------------------------------------
__global__ void roundcopy_kernel(const float* __restrict__ src, float* __restrict__ dst) {
    size_t i = (size_t)blockIdx.x * 256 + threadIdx.x;
    float4 v = ((const float4*)src)[i];
    v.x = tf32r(v.x); v.y = tf32r(v.y); v.z = tf32r(v.z); v.w = tf32r(v.w);
    ((float4*)dst)[i] = v;
}

// ---------------- router -----------------------------------------------------
__global__ void zero_kernel() {
    if (threadIdx.x < NEXP) g_cnt[threadIdx.x] = 0;
}

__global__ void router_kernel(const float* __restrict__ x,
                              const float* __restrict__ rw,
                              const float* __restrict__ rb) {
    int wid = threadIdx.x >> 5, lane = threadIdx.x & 31;
    int t = blockIdx.x * 8 + wid;
    if (t >= T_TOK) return;
    const float* xrow = x + (size_t)t * DIM;
    float lg[NEXP] = {0.f,0.f,0.f,0.f,0.f,0.f,0.f,0.f};
    for (int j = lane; j < DIM; j += 32) {
        float xv = xrow[j];
        const float* w = rw + (size_t)j * NEXP;
        #pragma unroll
        for (int e = 0; e < NEXP; e++) lg[e] += xv * w[e];
    }
    #pragma unroll
    for (int e = 0; e < NEXP; e++)
        #pragma unroll
        for (int o = 16; o > 0; o >>= 1)
            lg[e] += __shfl_xor_sync(0xffffffffu, lg[e], o);
    if (lane == 0) {
        float p[NEXP];
        #pragma unroll
        for (int e = 0; e < NEXP; e++) lg[e] += rb[e];
        float m = lg[0];
        #pragma unroll
        for (int e = 1; e < NEXP; e++) m = fmaxf(m, lg[e]);
        float s = 0.f;
        #pragma unroll
        for (int e = 0; e < NEXP; e++) { p[e] = __expf(lg[e] - m); s += p[e]; }
        #pragma unroll
        for (int e = 0; e < NEXP; e++) p[e] /= s;
        int e0 = 0;
        #pragma unroll
        for (int e = 1; e < NEXP; e++) if (p[e] > p[e0]) e0 = e;
        int e1 = (e0 == 0) ? 1 : 0;
        #pragma unroll
        for (int e = 0; e < NEXP; e++) if (e != e0 && p[e] > p[e1]) e1 = e;
        float den = p[e0] + p[e1] + 1e-20f;
        int pos0 = atomicAdd(&g_cnt[e0], 1);
        g_tok[e0 * T_TOK + pos0] = t;
        g_slot[2 * t]     = e0 * T_TOK + pos0;
        g_cw[2 * t]       = p[e0] / den;
        int pos1 = atomicAdd(&g_cnt[e1], 1);
        g_tok[e1 * T_TOK + pos1] = t;
        g_slot[2 * t + 1] = e1 * T_TOK + pos1;
        g_cw[2 * t + 1]   = p[e1] / den;
    }
}

// ---------------- stage 1: H = silu(X@G) * (X@U), cp.async pipeline ---------
__global__ void __launch_bounds__(256, 2) ffn1_cp(
    const float* __restrict__ xr,
    const float* __restrict__ gw_base,
    const float* __restrict__ uw_base,
    int mode)
{
    int e   = blockIdx.z;
    int cnt = mode ? T_TOK : g_cnt[e];
    int m0  = blockIdx.x * BM;
    if (m0 >= cnt) return;
    int n0  = blockIdx.y * BN;

    const int* tok = mode ? nullptr : (g_tok + e * T_TOK);
    float* H = mode ? g_Hs : (g_H + (size_t)e * T_TOK * FDIM);
    const float* gw = gw_base + (size_t)e * DIM * FDIM;
    const float* uw = uw_base + (size_t)e * DIM * FDIM;

    extern __shared__ char smem[];
    uint32_t sb = smem_u32(smem);
    int tid  = threadIdx.x;
    int lane = tid & 31, wid = tid >> 5;
    int wm = wid & 1, wn = wid >> 1;

    const char* aSrc[2]; uint32_t aZ[2], aDst[2];
    #pragma unroll
    for (int j = 0; j < 2; j++) {
        int idx = tid + j * 256;
        int row = idx >> 2, seg = idx & 3;
        aDst[j] = (uint32_t)(row * (ASTR * 4) + seg * 16);
        int grow = m0 + row;
        bool v = grow < cnt;
        int tk = v ? (tok ? tok[grow] : grow) : 0;
        aSrc[j] = (const char*)(xr + (size_t)tk * DIM) + seg * 16;
        aZ[j] = v ? 16u : 0u;
    }
    int brow = tid >> 4, bseg = tid & 15;
    uint32_t bDst = (uint32_t)(brow * (BSTR * 4) + bseg * 16);
    const char* gSrc = (const char*)(gw + (size_t)brow * FDIM + n0) + bseg * 16;
    const char* uSrc = (const char*)(uw + (size_t)brow * FDIM + n0) + bseg * 16;
    const size_t bStep = (size_t)BK * FDIM * 4;

    float cg[4][2][4] = {};
    float cu[4][2][4] = {};

    auto issue = [&](int k) {
        uint32_t base = sb + (uint32_t)(k & 3) * ST1_BYTES;
        cpa16(base + aDst[0], aSrc[0] + (size_t)k * 64, aZ[0]);
        cpa16(base + aDst[1], aSrc[1] + (size_t)k * 64, aZ[1]);
        cpa16(base + A_BYTES + bDst,           gSrc + (size_t)k * bStep, 16u);
        cpa16(base + A_BYTES + B_BYTES + bDst, uSrc + (size_t)k * bStep, 16u);
        CP_COMMIT();
    };

    issue(0); issue(1); issue(2);
    const int KIT = DIM / BK;  // 64
    for (int k = 0; k < KIT; k++) {
        CP_WAIT2();
        __syncthreads();
        const float* As = (const float*)(smem + (k & 3) * ST1_BYTES);
        const float* Bg = (const float*)(smem + (k & 3) * ST1_BYTES + A_BYTES);
        const float* Bu = (const float*)(smem + (k & 3) * ST1_BYTES + A_BYTES + B_BYTES);

        #pragma unroll
        for (int ks = 0; ks < BK; ks += 8) {
            uint32_t af[4][4];
            #pragma unroll
            for (int mi = 0; mi < 4; mi++) {
                int r = wm * 64 + mi * 16 + (lane >> 2);
                int c = ks + (lane & 3);
                af[mi][0] = __float_as_uint(As[r * ASTR + c]);
                af[mi][1] = __float_as_uint(As[(r + 8) * ASTR + c]);
                af[mi][2] = __float_as_uint(As[r * ASTR + c + 4]);
                af[mi][3] = __float_as_uint(As[(r + 8) * ASTR + c + 4]);
            }
            uint32_t bgf[2][2], buf2[2][2];
            #pragma unroll
            for (int ni = 0; ni < 2; ni++) {
                int cc = wn * 16 + ni * 8 + (lane >> 2);
                int kk = ks + (lane & 3);
                bgf[ni][0]  = __float_as_uint(Bg[kk * BSTR + cc]);
                bgf[ni][1]  = __float_as_uint(Bg[(kk + 4) * BSTR + cc]);
                buf2[ni][0] = __float_as_uint(Bu[kk * BSTR + cc]);
                buf2[ni][1] = __float_as_uint(Bu[(kk + 4) * BSTR + cc]);
            }
            #pragma unroll
            for (int mi = 0; mi < 4; mi++) {
                #pragma unroll
                for (int ni = 0; ni < 2; ni++) {
                    mma_tf32(cg[mi][ni], af[mi], bgf[ni]);
                    mma_tf32(cu[mi][ni], af[mi], buf2[ni]);
                }
            }
        }
        if (k + 3 < KIT) issue(k + 3); else CP_COMMIT();
    }

    #pragma unroll
    for (int mi = 0; mi < 4; mi++) {
        #pragma unroll
        for (int ni = 0; ni < 2; ni++) {
            int rbase = m0 + wm * 64 + mi * 16 + (lane >> 2);
            int cbase = n0 + wn * 16 + ni * 8 + (lane & 3) * 2;
            #pragma unroll
            for (int h = 0; h < 2; h++) {
                int row = rbase + h * 8;
                if (row < cnt) {
                    float g0 = cg[mi][ni][h * 2 + 0], g1 = cg[mi][ni][h * 2 + 1];
                    float u0 = cu[mi][ni][h * 2 + 0], u1 = cu[mi][ni][h * 2 + 1];
                    float h0 = tf32r(g0 / (1.f + __expf(-g0)) * u0);
                    float h1 = tf32r(g1 / (1.f + __expf(-g1)) * u1);
                    H[(size_t)row * FDIM + cbase]     = h0;
                    H[(size_t)row * FDIM + cbase + 1] = h1;
                }
            }
        }
    }
}

// ---------------- stage 2: Y = H @ down, BN=128, warp tile 64x32 -------------
__global__ void __launch_bounds__(256, 2) ffn2_cp(
    const float* __restrict__ dw_base,
    int mode)
{
    int e   = blockIdx.z;
    int cnt = mode ? T_TOK : g_cnt[e];
    int m0  = blockIdx.x * BM;
    if (m0 >= cnt) return;
    int n0  = blockIdx.y * BN2;

    const float* A  = mode ? g_Hs : (g_H + (size_t)e * T_TOK * FDIM);
    const float* dw = dw_base + (size_t)e * FDIM * DIM;
    float* Y = mode ? g_Ys : (g_Yr + (size_t)e * T_TOK * DIM);

    extern __shared__ char smem[];
    uint32_t sb = smem_u32(smem);
    int tid  = threadIdx.x;
    int lane = tid & 31, wid = tid >> 5;
    int wm = wid & 1, wn = wid >> 1;   // wm: 0..1 (64 rows), wn: 0..3 (32 cols)

    const char* aSrc[2]; uint32_t aZ[2], aDst[2];
    #pragma unroll
    for (int j = 0; j < 2; j++) {
        int idx = tid + j * 256;
        int row = idx >> 2, seg = idx & 3;
        aDst[j] = (uint32_t)(row * (ASTR * 4) + seg * 16);
        int grow = m0 + row;
        bool v = grow < cnt;
        aSrc[j] = (const char*)(A + (size_t)(v ? grow : 0) * FDIM) + seg * 16;
        aZ[j] = v ? 16u : 0u;
    }
    // B: 16 rows x 128 cols = 512 x 16B, 2 per thread
    uint32_t bDst[2]; const char* bSrc[2];
    #pragma unroll
    for (int j = 0; j < 2; j++) {
        int idx = tid + j * 256;
        int row = idx >> 5, seg = idx & 31;
        bDst[j] = (uint32_t)(row * (BSTR2 * 4) + seg * 16);
        bSrc[j] = (const char*)(dw + (size_t)row * DIM + n0) + seg * 16;
    }
    const size_t bStep = (size_t)BK * DIM * 4;

    float cc_[4][4][4] = {};

    auto issue = [&](int k) {
        uint32_t base = sb + (uint32_t)(k & 3) * ST2_BYTES;
        cpa16(base + aDst[0], aSrc[0] + (size_t)k * 64, aZ[0]);
        cpa16(base + aDst[1], aSrc[1] + (size_t)k * 64, aZ[1]);
        cpa16(base + A_BYTES + bDst[0], bSrc[0] + (size_t)k * bStep, 16u);
        cpa16(base + A_BYTES + bDst[1], bSrc[1] + (size_t)k * bStep, 16u);
        CP_COMMIT();
    };

    issue(0); issue(1); issue(2);
    const int KIT = FDIM / BK;  // 172
    for (int k = 0; k < KIT; k++) {
        CP_WAIT2();
        __syncthreads();
        const float* As = (const float*)(smem + (k & 3) * ST2_BYTES);
        const float* Bs = (const float*)(smem + (k & 3) * ST2_BYTES + A_BYTES);

        #pragma unroll
        for (int ks = 0; ks < BK; ks += 8) {
            uint32_t af[4][4];
            #pragma unroll
            for (int mi = 0; mi < 4; mi++) {
                int r = wm * 64 + mi * 16 + (lane >> 2);
                int c = ks + (lane & 3);
                af[mi][0] = __float_as_uint(As[r * ASTR + c]);
                af[mi][1] = __float_as_uint(As[(r + 8) * ASTR + c]);
                af[mi][2] = __float_as_uint(As[r * ASTR + c + 4]);
                af[mi][3] = __float_as_uint(As[(r + 8) * ASTR + c + 4]);
            }
            uint32_t bf[4][2];
            #pragma unroll
            for (int ni = 0; ni < 4; ni++) {
                int ccc = wn * 32 + ni * 8 + (lane >> 2);
                int kk  = ks + (lane & 3);
                bf[ni][0] = __float_as_uint(Bs[kk * BSTR2 + ccc]);
                bf[ni][1] = __float_as_uint(Bs[(kk + 4) * BSTR2 + ccc]);
            }
            #pragma unroll
            for (int mi = 0; mi < 4; mi++)
                #pragma unroll
                for (int ni = 0; ni < 4; ni++)
                    mma_tf32(cc_[mi][ni], af[mi], bf[ni]);
        }
        if (k + 3 < KIT) issue(k + 3); else CP_COMMIT();
    }

    #pragma unroll
    for (int mi = 0; mi < 4; mi++) {
        #pragma unroll
        for (int ni = 0; ni < 4; ni++) {
            int rbase = m0 + wm * 64 + mi * 16 + (lane >> 2);
            int cbase = n0 + wn * 32 + ni * 8 + (lane & 3) * 2;
            #pragma unroll
            for (int h = 0; h < 2; h++) {
                int row = rbase + h * 8;
                if (row < cnt) {
                    Y[(size_t)row * DIM + cbase]     = cc_[mi][ni][h * 2 + 0];
                    Y[(size_t)row * DIM + cbase + 1] = cc_[mi][ni][h * 2 + 1];
                }
            }
        }
    }
}

// ---------------- combine ----------------------------------------------------
__global__ void combine_kernel(float* __restrict__ out) {
    int i  = blockIdx.x * blockDim.x + threadIdx.x;
    int t  = i / (DIM / 4);
    int dv = (i % (DIM / 4)) * 4;
    float w0 = g_cw[2 * t], w1 = g_cw[2 * t + 1];
    size_t s0 = (size_t)g_slot[2 * t] * DIM + dv;
    size_t s1 = (size_t)g_slot[2 * t + 1] * DIM + dv;
    float4 a = *(const float4*)(g_Yr + s0);
    float4 b = *(const float4*)(g_Yr + s1);
    float4 c = *(const float4*)(g_Ys + (size_t)t * DIM + dv);
    float4 o;
    o.x = w0 * a.x + w1 * b.x + c.x;
    o.y = w0 * a.y + w1 * b.y + c.y;
    o.z = w0 * a.z + w1 * b.z + c.z;
    o.w = w0 * a.w + w1 * b.w + c.w;
    *(float4*)(out + (size_t)t * DIM + dv) = o;
}

// ---------------- launch ------------------------------------------------------
extern "C" void kernel_launch(void* const* d_in, const int* in_sizes, int n_in,
                              void* d_out, int out_size) {
    const float* x   = (const float*)d_in[0];
    const float* rw  = (const float*)d_in[1];
    const float* rb  = (const float*)d_in[2];
    const float* gw  = (const float*)d_in[3];
    const float* uw  = (const float*)d_in[4];
    const float* dw  = (const float*)d_in[5];
    const float* sgw = (const float*)d_in[6];
    const float* suw = (const float*)d_in[7];
    const float* sdw = (const float*)d_in[8];
    float* out = (float*)d_out;

    cudaFuncSetAttribute(ffn1_cp, cudaFuncAttributeMaxDynamicSharedMemorySize, SMEM1);
    cudaFuncSetAttribute(ffn2_cp, cudaFuncAttributeMaxDynamicSharedMemorySize, SMEM2);

    float *xr, *gwR, *uwR, *dwR, *sgwR, *suwR, *sdwR;
    cudaGetSymbolAddress((void**)&xr,   g_xr);
    cudaGetSymbolAddress((void**)&gwR,  g_gwR);
    cudaGetSymbolAddress((void**)&uwR,  g_uwR);
    cudaGetSymbolAddress((void**)&dwR,  g_dwR);
    cudaGetSymbolAddress((void**)&sgwR, g_sgwR);
    cudaGetSymbolAddress((void**)&suwR, g_suwR);
    cudaGetSymbolAddress((void**)&sdwR, g_sdwR);

    // ordered so launch #6 (ncu -s 5 -c 1) is the routed ffn1
    roundcopy_kernel<<<(T_TOK * DIM) / 1024, 256>>>(x, xr);                                  // 1
    roundcopy_kernel<<<(int)(((size_t)NEXP * DIM * FDIM) / 1024), 256>>>(gw, gwR);           // 2
    roundcopy_kernel<<<(int)(((size_t)NEXP * DIM * FDIM) / 1024), 256>>>(uw, uwR);           // 3
    zero_kernel<<<1, 32>>>();                                                                // 4
    router_kernel<<<T_TOK / 8, 256>>>(x, rw, rb);                                            // 5

    dim3 g1(T_TOK / BM, FDIM / BN, NEXP);   // 64 x 43 x 8
    ffn1_cp<<<g1, 256, SMEM1>>>(xr, gwR, uwR, 0);                                            // 6 <- profiled

    roundcopy_kernel<<<(DIM * FDIM) / 1024, 256>>>(sgw, sgwR);                               // 7
    roundcopy_kernel<<<(DIM * FDIM) / 1024, 256>>>(suw, suwR);                               // 8
    dim3 g1s(T_TOK / BM, FDIM / BN, 1);
    ffn1_cp<<<g1s, 256, SMEM1>>>(xr, sgwR, suwR, 1);                                         // 9

    roundcopy_kernel<<<(int)(((size_t)NEXP * FDIM * DIM) / 1024), 256>>>(dw, dwR);           // 10
    dim3 g2(T_TOK / BM, DIM / BN2, NEXP);   // 64 x 8 x 8
    ffn2_cp<<<g2, 256, SMEM2>>>(dwR, 0);                                                     // 11

    roundcopy_kernel<<<(FDIM * DIM) / 1024, 256>>>(sdw, sdwR);                               // 12
    dim3 g2s(T_TOK / BM, DIM / BN2, 1);
    ffn2_cp<<<g2s, 256, SMEM2>>>(sdwR, 1);                                                   // 13

    combine_kernel<<<(T_TOK * (DIM / 4)) / 256, 256>>>(out);                                 // 14
}

// round 5
// speedup vs baseline: 2.3042x; 1.6076x over previous
#include <cuda_runtime.h>
#include <cuda_fp16.h>
#include <cstdint>
#include <cstddef>

#define T_TOK 8192
#define DIM   1024
#define FDIM  2752
#define NEXP  8

#define BM 128
#define BK 32
#define ASTRH 40                     // halves per A/B smem row (32 + 8 pad)
#define A_BYTES (BM * ASTRH * 2)     // 10240
#define B_BYTES (128 * ASTRH * 2)    // 10240 (128 B-rows both stages)
#define ST_BYTES (A_BYTES + B_BYTES) // 20480
#define STAGES 4
#define SMEM_SZ (STAGES * ST_BYTES)  // 81920

// ---------------- scratch ----------------------------------------------------
__device__ int    g_cnt[NEXP];
__device__ int    g_tok[NEXP * T_TOK];
__device__ int    g_slot[T_TOK * 2];
__device__ float  g_cw[T_TOK * 2];
__device__ __half g_xH [(size_t)T_TOK * DIM];
__device__ __half g_gwH[(size_t)NEXP * FDIM * DIM];   // [N=F][K=D] per expert
__device__ __half g_uwH[(size_t)NEXP * FDIM * DIM];
__device__ __half g_dwH[(size_t)NEXP * DIM * FDIM];   // [N=D][K=F] per expert
__device__ __half g_sgwH[(size_t)FDIM * DIM];
__device__ __half g_suwH[(size_t)FDIM * DIM];
__device__ __half g_sdwH[(size_t)DIM * FDIM];
__device__ __half g_H  [(size_t)NEXP * T_TOK * FDIM];
__device__ __half g_Hs [(size_t)T_TOK * FDIM];
__device__ float  g_Yr [(size_t)NEXP * T_TOK * DIM];
__device__ float  g_Ys [(size_t)T_TOK * DIM];

// ---------------- helpers ----------------------------------------------------
__device__ __forceinline__ uint32_t smem_u32(const void* p) {
    uint32_t a;
    asm("{ .reg .u64 t; cvta.to.shared.u64 t, %1; cvt.u32.u64 %0, t; }" : "=r"(a) : "l"(p));
    return a;
}
__device__ __forceinline__ void cpa16(uint32_t dst, const void* src, uint32_t nbytes) {
    asm volatile("cp.async.cg.shared.global [%0], [%1], 16, %2;"
                 :: "r"(dst), "l"(src), "r"(nbytes) : "memory");
}
#define CP_COMMIT() asm volatile("cp.async.commit_group;" ::: "memory")
#define CP_WAIT2()  asm volatile("cp.async.wait_group 2;" ::: "memory")

__device__ __forceinline__ void mma_f16(float* c, const uint32_t* a, const uint32_t* b) {
    asm volatile(
        "mma.sync.aligned.m16n8k16.row.col.f32.f16.f16.f32 "
        "{%0,%1,%2,%3}, {%4,%5,%6,%7}, {%8,%9}, {%0,%1,%2,%3};\n"
        : "+f"(c[0]), "+f"(c[1]), "+f"(c[2]), "+f"(c[3])
        : "r"(a[0]), "r"(a[1]), "r"(a[2]), "r"(a[3]),
          "r"(b[0]), "r"(b[1]));
}

// ---------------- prep: x -> fp16 (+ zero counters) --------------------------
__global__ void cvtx_zero_kernel(const float* __restrict__ x, __half* __restrict__ xh) {
    if (blockIdx.x == 0 && threadIdx.x < NEXP) g_cnt[threadIdx.x] = 0;
    size_t i = ((size_t)blockIdx.x * 256 + threadIdx.x) * 4;
    float4 v = *(const float4*)(x + i);
    __half2* o = (__half2*)(xh + i);
    o[0] = __floats2half2_rn(v.x, v.y);
    o[1] = __floats2half2_rn(v.z, v.w);
}

// ---------------- prep: transpose+convert weights to [N][K] fp16 -------------
// src fp32 [R][C] (+ e*R*C), dst fp16 [C][R] (+ e*R*C). two=1: z=(e<<1)|mat.
__global__ void cvt_trans(const float* __restrict__ s0, const float* __restrict__ s1,
                          __half* __restrict__ d0, __half* __restrict__ d1,
                          int R, int C, int two) {
    __shared__ float tile[32][33];
    int z = blockIdx.z, m = two ? (z & 1) : 0, e = two ? (z >> 1) : z;
    const float* src = (m ? s1 : s0) + (size_t)e * R * C;
    __half* dst = (m ? d1 : d0) + (size_t)e * R * C;
    int r0 = blockIdx.x * 32, c0 = blockIdx.y * 32;
    int tx = threadIdx.x, ty = threadIdx.y;
    #pragma unroll
    for (int i = 0; i < 4; i++)
        tile[ty + i * 8][tx] = src[(size_t)(r0 + ty + i * 8) * C + c0 + tx];
    __syncthreads();
    #pragma unroll
    for (int i = 0; i < 4; i++)
        dst[(size_t)(c0 + ty + i * 8) * R + r0 + tx] = __float2half(tile[tx][ty + i * 8]);
}

// ---------------- router -----------------------------------------------------
__global__ void router_kernel(const float* __restrict__ x,
                              const float* __restrict__ rw,
                              const float* __restrict__ rb) {
    int wid = threadIdx.x >> 5, lane = threadIdx.x & 31;
    int t = blockIdx.x * 8 + wid;
    if (t >= T_TOK) return;
    const float* xrow = x + (size_t)t * DIM;
    float lg[NEXP] = {0.f,0.f,0.f,0.f,0.f,0.f,0.f,0.f};
    for (int j = lane; j < DIM; j += 32) {
        float xv = xrow[j];
        const float* w = rw + (size_t)j * NEXP;
        #pragma unroll
        for (int e = 0; e < NEXP; e++) lg[e] += xv * w[e];
    }
    #pragma unroll
    for (int e = 0; e < NEXP; e++)
        #pragma unroll
        for (int o = 16; o > 0; o >>= 1)
            lg[e] += __shfl_xor_sync(0xffffffffu, lg[e], o);
    if (lane == 0) {
        float p[NEXP];
        #pragma unroll
        for (int e = 0; e < NEXP; e++) lg[e] += rb[e];
        float m = lg[0];
        #pragma unroll
        for (int e = 1; e < NEXP; e++) m = fmaxf(m, lg[e]);
        float s = 0.f;
        #pragma unroll
        for (int e = 0; e < NEXP; e++) { p[e] = __expf(lg[e] - m); s += p[e]; }
        #pragma unroll
        for (int e = 0; e < NEXP; e++) p[e] /= s;
        int e0 = 0;
        #pragma unroll
        for (int e = 1; e < NEXP; e++) if (p[e] > p[e0]) e0 = e;
        int e1 = (e0 == 0) ? 1 : 0;
        #pragma unroll
        for (int e = 0; e < NEXP; e++) if (e != e0 && p[e] > p[e1]) e1 = e;
        float den = p[e0] + p[e1] + 1e-20f;
        int pos0 = atomicAdd(&g_cnt[e0], 1);
        g_tok[e0 * T_TOK + pos0] = t;
        g_slot[2 * t]     = e0 * T_TOK + pos0;
        g_cw[2 * t]       = p[e0] / den;
        int pos1 = atomicAdd(&g_cnt[e1], 1);
        g_tok[e1 * T_TOK + pos1] = t;
        g_slot[2 * t + 1] = e1 * T_TOK + pos1;
        g_cw[2 * t + 1]   = p[e1] / den;
    }
}

// ---------------- stage 1: H = silu(X@G)*(X@U), fp16 mma, cp.async -----------
// BM=128, gate N=64 + up N=64 (B rows 0-63 gate, 64-127 up), BK=32
__global__ void __launch_bounds__(256, 2) ffn1_h(
    const __half* __restrict__ xh,
    const __half* __restrict__ gw_base,
    const __half* __restrict__ uw_base,
    int mode)
{
    int e   = blockIdx.z;
    int cnt = mode ? T_TOK : g_cnt[e];
    int m0  = blockIdx.x * BM;
    if (m0 >= cnt) return;
    int n0  = blockIdx.y * 64;

    const int* tok = mode ? nullptr : (g_tok + e * T_TOK);
    __half* H = mode ? g_Hs : (g_H + (size_t)e * T_TOK * FDIM);
    const __half* gwe = gw_base + (size_t)e * FDIM * DIM;
    const __half* uwe = uw_base + (size_t)e * FDIM * DIM;

    extern __shared__ char smem[];
    uint32_t sb = smem_u32(smem);
    int tid  = threadIdx.x;
    int lane = tid & 31, wid = tid >> 5;
    int wm = wid & 1, wn = wid >> 1;   // wm: 64-row half; wn: 16-col slice

    const char* aSrc[2]; uint32_t aZ[2], aDst[2];
    const char* bSrc[2]; uint32_t bDst[2];
    #pragma unroll
    for (int j = 0; j < 2; j++) {
        int idx = tid + j * 256;
        int row = idx >> 2, seg = idx & 3;
        aDst[j] = (uint32_t)(row * (ASTRH * 2) + seg * 16);
        int grow = m0 + row;
        bool v = grow < cnt;
        int tk = v ? (tok ? tok[grow] : grow) : 0;
        aSrc[j] = (const char*)(xh + (size_t)tk * DIM + seg * 8);
        aZ[j] = v ? 16u : 0u;
        bDst[j] = (uint32_t)(A_BYTES + row * (ASTRH * 2) + seg * 16);
        bSrc[j] = (const char*)((row < 64 ? gwe + (size_t)(n0 + row) * DIM
                                          : uwe + (size_t)(n0 + row - 64) * DIM) + seg * 8);
    }

    float cg[4][2][4] = {};
    float cu[4][2][4] = {};

    auto issue = [&](int k) {
        uint32_t base = sb + (uint32_t)(k & 3) * ST_BYTES;
        cpa16(base + aDst[0], aSrc[0] + (size_t)k * 64, aZ[0]);
        cpa16(base + aDst[1], aSrc[1] + (size_t)k * 64, aZ[1]);
        cpa16(base + bDst[0], bSrc[0] + (size_t)k * 64, 16u);
        cpa16(base + bDst[1], bSrc[1] + (size_t)k * 64, 16u);
        CP_COMMIT();
    };

    issue(0); issue(1); issue(2);
    const int KIT = DIM / BK;  // 32
    for (int k = 0; k < KIT; k++) {
        CP_WAIT2();
        __syncthreads();
        const __half* As = (const __half*)(smem + (k & 3) * ST_BYTES);
        const __half* Bs = (const __half*)(smem + (k & 3) * ST_BYTES + A_BYTES);

        #pragma unroll
        for (int ks = 0; ks < 2; ks++) {
            int kc = ks * 16 + (lane & 3) * 2;
            uint32_t af[4][4];
            #pragma unroll
            for (int mi = 0; mi < 4; mi++) {
                int r = wm * 64 + mi * 16 + (lane >> 2);
                af[mi][0] = *(const uint32_t*)(As + r * ASTRH + kc);
                af[mi][1] = *(const uint32_t*)(As + (r + 8) * ASTRH + kc);
                af[mi][2] = *(const uint32_t*)(As + r * ASTRH + kc + 8);
                af[mi][3] = *(const uint32_t*)(As + (r + 8) * ASTRH + kc + 8);
            }
            uint32_t bg[2][2], bu[2][2];
            #pragma unroll
            for (int ni = 0; ni < 2; ni++) {
                int n = wn * 16 + ni * 8 + (lane >> 2);
                bg[ni][0] = *(const uint32_t*)(Bs + n * ASTRH + kc);
                bg[ni][1] = *(const uint32_t*)(Bs + n * ASTRH + kc + 8);
                bu[ni][0] = *(const uint32_t*)(Bs + (64 + n) * ASTRH + kc);
                bu[ni][1] = *(const uint32_t*)(Bs + (64 + n) * ASTRH + kc + 8);
            }
            #pragma unroll
            for (int mi = 0; mi < 4; mi++) {
                #pragma unroll
                for (int ni = 0; ni < 2; ni++) {
                    mma_f16(cg[mi][ni], af[mi], bg[ni]);
                    mma_f16(cu[mi][ni], af[mi], bu[ni]);
                }
            }
        }
        if (k + 3 < KIT) issue(k + 3); else CP_COMMIT();
    }

    #pragma unroll
    for (int mi = 0; mi < 4; mi++) {
        #pragma unroll
        for (int ni = 0; ni < 2; ni++) {
            int rbase = m0 + wm * 64 + mi * 16 + (lane >> 2);
            int cbase = n0 + wn * 16 + ni * 8 + (lane & 3) * 2;
            #pragma unroll
            for (int h = 0; h < 2; h++) {
                int row = rbase + h * 8;
                if (row < cnt) {
                    float g0 = cg[mi][ni][h * 2 + 0], g1 = cg[mi][ni][h * 2 + 1];
                    float u0 = cu[mi][ni][h * 2 + 0], u1 = cu[mi][ni][h * 2 + 1];
                    float h0 = g0 / (1.f + __expf(-g0)) * u0;
                    float h1 = g1 / (1.f + __expf(-g1)) * u1;
                    *(__half2*)(H + (size_t)row * FDIM + cbase) = __floats2half2_rn(h0, h1);
                }
            }
        }
    }
}

// ---------------- stage 2: Y = H @ down, fp16 mma, BN=128 --------------------
__global__ void __launch_bounds__(256, 2) ffn2_h(
    const __half* __restrict__ dw_base,
    int mode)
{
    int e   = blockIdx.z;
    int cnt = mode ? T_TOK : g_cnt[e];
    int m0  = blockIdx.x * BM;
    if (m0 >= cnt) return;
    int n0  = blockIdx.y * 128;

    const __half* A  = mode ? g_Hs : (g_H + (size_t)e * T_TOK * FDIM);
    const __half* dwe = dw_base + (size_t)e * DIM * FDIM;
    float* Y = mode ? g_Ys : (g_Yr + (size_t)e * T_TOK * DIM);

    extern __shared__ char smem[];
    uint32_t sb = smem_u32(smem);
    int tid  = threadIdx.x;
    int lane = tid & 31, wid = tid >> 5;
    int wm = wid & 1, wn = wid >> 1;   // warp tile 64x32

    const char* aSrc[2]; uint32_t aZ[2], aDst[2];
    const char* bSrc[2]; uint32_t bDst[2];
    #pragma unroll
    for (int j = 0; j < 2; j++) {
        int idx = tid + j * 256;
        int row = idx >> 2, seg = idx & 3;
        aDst[j] = (uint32_t)(row * (ASTRH * 2) + seg * 16);
        int grow = m0 + row;
        bool v = grow < cnt;
        aSrc[j] = (const char*)(A + (size_t)(v ? grow : 0) * FDIM + seg * 8);
        aZ[j] = v ? 16u : 0u;
        bDst[j] = (uint32_t)(A_BYTES + row * (ASTRH * 2) + seg * 16);
        bSrc[j] = (const char*)(dwe + (size_t)(n0 + row) * FDIM + seg * 8);
    }

    float cc_[4][4][4] = {};

    auto issue = [&](int k) {
        uint32_t base = sb + (uint32_t)(k & 3) * ST_BYTES;
        cpa16(base + aDst[0], aSrc[0] + (size_t)k * 64, aZ[0]);
        cpa16(base + aDst[1], aSrc[1] + (size_t)k * 64, aZ[1]);
        cpa16(base + bDst[0], bSrc[0] + (size_t)k * 64, 16u);
        cpa16(base + bDst[1], bSrc[1] + (size_t)k * 64, 16u);
        CP_COMMIT();
    };

    issue(0); issue(1); issue(2);
    const int KIT = FDIM / BK;  // 86
    for (int k = 0; k < KIT; k++) {
        CP_WAIT2();
        __syncthreads();
        const __half* As = (const __half*)(smem + (k & 3) * ST_BYTES);
        const __half* Bs = (const __half*)(smem + (k & 3) * ST_BYTES + A_BYTES);

        #pragma unroll
        for (int ks = 0; ks < 2; ks++) {
            int kc = ks * 16 + (lane & 3) * 2;
            uint32_t af[4][4];
            #pragma unroll
            for (int mi = 0; mi < 4; mi++) {
                int r = wm * 64 + mi * 16 + (lane >> 2);
                af[mi][0] = *(const uint32_t*)(As + r * ASTRH + kc);
                af[mi][1] = *(const uint32_t*)(As + (r + 8) * ASTRH + kc);
                af[mi][2] = *(const uint32_t*)(As + r * ASTRH + kc + 8);
                af[mi][3] = *(const uint32_t*)(As + (r + 8) * ASTRH + kc + 8);
            }
            uint32_t bf[4][2];
            #pragma unroll
            for (int ni = 0; ni < 4; ni++) {
                int n = wn * 32 + ni * 8 + (lane >> 2);
                bf[ni][0] = *(const uint32_t*)(Bs + n * ASTRH + kc);
                bf[ni][1] = *(const uint32_t*)(Bs + n * ASTRH + kc + 8);
            }
            #pragma unroll
            for (int mi = 0; mi < 4; mi++)
                #pragma unroll
                for (int ni = 0; ni < 4; ni++)
                    mma_f16(cc_[mi][ni], af[mi], bf[ni]);
        }
        if (k + 3 < KIT) issue(k + 3); else CP_COMMIT();
    }

    #pragma unroll
    for (int mi = 0; mi < 4; mi++) {
        #pragma unroll
        for (int ni = 0; ni < 4; ni++) {
            int rbase = m0 + wm * 64 + mi * 16 + (lane >> 2);
            int cbase = n0 + wn * 32 + ni * 8 + (lane & 3) * 2;
            #pragma unroll
            for (int h = 0; h < 2; h++) {
                int row = rbase + h * 8;
                if (row < cnt) {
                    Y[(size_t)row * DIM + cbase]     = cc_[mi][ni][h * 2 + 0];
                    Y[(size_t)row * DIM + cbase + 1] = cc_[mi][ni][h * 2 + 1];
                }
            }
        }
    }
}

// ---------------- combine ----------------------------------------------------
__global__ void combine_kernel(float* __restrict__ out) {
    int i  = blockIdx.x * blockDim.x + threadIdx.x;
    int t  = i / (DIM / 4);
    int dv = (i % (DIM / 4)) * 4;
    float w0 = g_cw[2 * t], w1 = g_cw[2 * t + 1];
    size_t s0 = (size_t)g_slot[2 * t] * DIM + dv;
    size_t s1 = (size_t)g_slot[2 * t + 1] * DIM + dv;
    float4 a = *(const float4*)(g_Yr + s0);
    float4 b = *(const float4*)(g_Yr + s1);
    float4 c = *(const float4*)(g_Ys + (size_t)t * DIM + dv);
    float4 o;
    o.x = w0 * a.x + w1 * b.x + c.x;
    o.y = w0 * a.y + w1 * b.y + c.y;
    o.z = w0 * a.z + w1 * b.z + c.z;
    o.w = w0 * a.w + w1 * b.w + c.w;
    *(float4*)(out + (size_t)t * DIM + dv) = o;
}

// ---------------- launch ------------------------------------------------------
extern "C" void kernel_launch(void* const* d_in, const int* in_sizes, int n_in,
                              void* d_out, int out_size) {
    const float* x   = (const float*)d_in[0];
    const float* rw  = (const float*)d_in[1];
    const float* rb  = (const float*)d_in[2];
    const float* gw  = (const float*)d_in[3];
    const float* uw  = (const float*)d_in[4];
    const float* dw  = (const float*)d_in[5];
    const float* sgw = (const float*)d_in[6];
    const float* suw = (const float*)d_in[7];
    const float* sdw = (const float*)d_in[8];
    float* out = (float*)d_out;

    cudaFuncSetAttribute(ffn1_h, cudaFuncAttributeMaxDynamicSharedMemorySize, SMEM_SZ);
    cudaFuncSetAttribute(ffn2_h, cudaFuncAttributeMaxDynamicSharedMemorySize, SMEM_SZ);

    __half *xh, *gwH, *uwH, *dwH, *sgwH, *suwH, *sdwH;
    cudaGetSymbolAddress((void**)&xh,   g_xH);
    cudaGetSymbolAddress((void**)&gwH,  g_gwH);
    cudaGetSymbolAddress((void**)&uwH,  g_uwH);
    cudaGetSymbolAddress((void**)&dwH,  g_dwH);
    cudaGetSymbolAddress((void**)&sgwH, g_sgwH);
    cudaGetSymbolAddress((void**)&suwH, g_suwH);
    cudaGetSymbolAddress((void**)&sdwH, g_sdwH);

    dim3 tb(32, 8);

    cvtx_zero_kernel<<<(T_TOK * DIM) / 1024, 256>>>(x, xh);                       // 1
    router_kernel<<<T_TOK / 8, 256>>>(x, rw, rb);                                 // 2
    cvt_trans<<<dim3(DIM/32, FDIM/32, 2*NEXP), tb>>>(gw, uw, gwH, uwH,
                                                     DIM, FDIM, 1);               // 3
    dim3 g1(T_TOK / BM, FDIM / 64, NEXP);   // 64 x 43 x 8
    ffn1_h<<<g1, 256, SMEM_SZ>>>(xh, gwH, uwH, 0);                                // 4 <- target profile
    cvt_trans<<<dim3(DIM/32, FDIM/32, 2), tb>>>(sgw, suw, sgwH, suwH,
                                                DIM, FDIM, 1);                    // 5
    dim3 g1s(T_TOK / BM, FDIM / 64, 1);
    ffn1_h<<<g1s, 256, SMEM_SZ>>>(xh, sgwH, suwH, 1);                             // 6
    cvt_trans<<<dim3(FDIM/32, DIM/32, NEXP), tb>>>(dw, dw, dwH, dwH,
                                                   FDIM, DIM, 0);                 // 7
    dim3 g2(T_TOK / BM, DIM / 128, NEXP);   // 64 x 8 x 8
    ffn2_h<<<g2, 256, SMEM_SZ>>>(dwH, 0);                                         // 8
    cvt_trans<<<dim3(FDIM/32, DIM/32, 1), tb>>>(sdw, sdw, sdwH, sdwH,
                                                FDIM, DIM, 0);                    // 9
    dim3 g2s(T_TOK / BM, DIM / 128, 1);
    ffn2_h<<<g2s, 256, SMEM_SZ>>>(sdwH, 1);                                       // 10
    combine_kernel<<<(T_TOK * (DIM / 4)) / 256, 256>>>(out);                      // 11
}

// round 6
// speedup vs baseline: 2.6520x; 1.1509x over previous
#include <cuda_runtime.h>
#include <cuda_fp16.h>
#include <cstdint>
#include <cstddef>

#define T_TOK 8192
#define DIM   1024
#define FDIM  2752
#define NEXP  8

#define BM 128
#define BK 32
#define ASTRH 40                     // halves per A/B smem row (32 + 8 pad)
#define A_BYTES (BM * ASTRH * 2)     // 10240
#define B_BYTES (128 * ASTRH * 2)    // 10240
#define ST_BYTES (A_BYTES + B_BYTES) // 20480
#define STAGES 4
#define SMEM_SZ (STAGES * ST_BYTES)  // 81920

// ---------------- scratch ----------------------------------------------------
__device__ int    g_cnt[NEXP];
__device__ int    g_tok[NEXP * T_TOK];
__device__ int    g_slot[T_TOK * 2];
__device__ float  g_cw[T_TOK * 2];
__device__ __half g_xH [(size_t)T_TOK * DIM];
__device__ __half g_gwH[(size_t)NEXP * FDIM * DIM];   // [N=F][K=D] per expert
__device__ __half g_uwH[(size_t)NEXP * FDIM * DIM];
__device__ __half g_dwH[(size_t)NEXP * DIM * FDIM];   // [N=D][K=F] per expert
__device__ __half g_sgwH[(size_t)FDIM * DIM];
__device__ __half g_suwH[(size_t)FDIM * DIM];
__device__ __half g_sdwH[(size_t)DIM * FDIM];
__device__ __half g_H  [(size_t)NEXP * T_TOK * FDIM];
__device__ __half g_Hs [(size_t)T_TOK * FDIM];
__device__ float  g_Yr [(size_t)NEXP * T_TOK * DIM];
__device__ float  g_Ys [(size_t)T_TOK * DIM];

// ---------------- helpers ----------------------------------------------------
__device__ __forceinline__ uint32_t smem_u32(const void* p) {
    uint32_t a;
    asm("{ .reg .u64 t; cvta.to.shared.u64 t, %1; cvt.u32.u64 %0, t; }" : "=r"(a) : "l"(p));
    return a;
}
__device__ __forceinline__ void cpa16(uint32_t dst, const void* src, uint32_t nbytes) {
    asm volatile("cp.async.cg.shared.global [%0], [%1], 16, %2;"
                 :: "r"(dst), "l"(src), "r"(nbytes) : "memory");
}
#define CP_COMMIT() asm volatile("cp.async.commit_group;" ::: "memory")
#define CP_WAIT2()  asm volatile("cp.async.wait_group 2;" ::: "memory")

__device__ __forceinline__ void mma_f16(float* c, const uint32_t* a, const uint32_t* b) {
    asm volatile(
        "mma.sync.aligned.m16n8k16.row.col.f32.f16.f16.f32 "
        "{%0,%1,%2,%3}, {%4,%5,%6,%7}, {%8,%9}, {%0,%1,%2,%3};\n"
        : "+f"(c[0]), "+f"(c[1]), "+f"(c[2]), "+f"(c[3])
        : "r"(a[0]), "r"(a[1]), "r"(a[2]), "r"(a[3]),
          "r"(b[0]), "r"(b[1]));
}
__device__ __forceinline__ void ldsm_x4(uint32_t& r0, uint32_t& r1, uint32_t& r2,
                                        uint32_t& r3, uint32_t a) {
    asm volatile("ldmatrix.sync.aligned.m8n8.x4.shared.b16 {%0,%1,%2,%3}, [%4];"
                 : "=r"(r0), "=r"(r1), "=r"(r2), "=r"(r3) : "r"(a));
}

// ---------------- prep: x -> fp16 (+ zero counters) --------------------------
__global__ void cvtx_zero_kernel(const float* __restrict__ x, __half* __restrict__ xh) {
    if (blockIdx.x == 0 && threadIdx.x < NEXP) g_cnt[threadIdx.x] = 0;
    size_t i = ((size_t)blockIdx.x * 256 + threadIdx.x) * 4;
    float4 v = *(const float4*)(x + i);
    __half2* o = (__half2*)(xh + i);
    o[0] = __floats2half2_rn(v.x, v.y);
    o[1] = __floats2half2_rn(v.z, v.w);
}

// ---------------- prep: transpose+convert weights to [N][K] fp16 -------------
__global__ void cvt_trans(const float* __restrict__ s0, const float* __restrict__ s1,
                          __half* __restrict__ d0, __half* __restrict__ d1,
                          int R, int C, int two) {
    __shared__ float tile[32][33];
    int z = blockIdx.z, m = two ? (z & 1) : 0, e = two ? (z >> 1) : z;
    const float* src = (m ? s1 : s0) + (size_t)e * R * C;
    __half* dst = (m ? d1 : d0) + (size_t)e * R * C;
    int r0 = blockIdx.x * 32, c0 = blockIdx.y * 32;
    int tx = threadIdx.x, ty = threadIdx.y;
    #pragma unroll
    for (int i = 0; i < 4; i++)
        tile[ty + i * 8][tx] = src[(size_t)(r0 + ty + i * 8) * C + c0 + tx];
    __syncthreads();
    #pragma unroll
    for (int i = 0; i < 4; i++)
        dst[(size_t)(c0 + ty + i * 8) * R + r0 + tx] = __float2half(tile[tx][ty + i * 8]);
}

// ---------------- router -----------------------------------------------------
__global__ void router_kernel(const float* __restrict__ x,
                              const float* __restrict__ rw,
                              const float* __restrict__ rb) {
    int wid = threadIdx.x >> 5, lane = threadIdx.x & 31;
    int t = blockIdx.x * 8 + wid;
    if (t >= T_TOK) return;
    const float* xrow = x + (size_t)t * DIM;
    float lg[NEXP] = {0.f,0.f,0.f,0.f,0.f,0.f,0.f,0.f};
    for (int j = lane; j < DIM; j += 32) {
        float xv = xrow[j];
        const float* w = rw + (size_t)j * NEXP;
        #pragma unroll
        for (int e = 0; e < NEXP; e++) lg[e] += xv * w[e];
    }
    #pragma unroll
    for (int e = 0; e < NEXP; e++)
        #pragma unroll
        for (int o = 16; o > 0; o >>= 1)
            lg[e] += __shfl_xor_sync(0xffffffffu, lg[e], o);
    if (lane == 0) {
        float p[NEXP];
        #pragma unroll
        for (int e = 0; e < NEXP; e++) lg[e] += rb[e];
        float m = lg[0];
        #pragma unroll
        for (int e = 1; e < NEXP; e++) m = fmaxf(m, lg[e]);
        float s = 0.f;
        #pragma unroll
        for (int e = 0; e < NEXP; e++) { p[e] = __expf(lg[e] - m); s += p[e]; }
        #pragma unroll
        for (int e = 0; e < NEXP; e++) p[e] /= s;
        int e0 = 0;
        #pragma unroll
        for (int e = 1; e < NEXP; e++) if (p[e] > p[e0]) e0 = e;
        int e1 = (e0 == 0) ? 1 : 0;
        #pragma unroll
        for (int e = 0; e < NEXP; e++) if (e != e0 && p[e] > p[e1]) e1 = e;
        float den = p[e0] + p[e1] + 1e-20f;
        int pos0 = atomicAdd(&g_cnt[e0], 1);
        g_tok[e0 * T_TOK + pos0] = t;
        g_slot[2 * t]     = e0 * T_TOK + pos0;
        g_cw[2 * t]       = p[e0] / den;
        int pos1 = atomicAdd(&g_cnt[e1], 1);
        g_tok[e1 * T_TOK + pos1] = t;
        g_slot[2 * t + 1] = e1 * T_TOK + pos1;
        g_cw[2 * t + 1]   = p[e1] / den;
    }
}

// ---------------- stage 1: H = silu(X@G)*(X@U), fp16 mma + ldmatrix ----------
__global__ void __launch_bounds__(256, 2) ffn1_h(
    const __half* __restrict__ xh,
    const __half* __restrict__ gw_base,
    const __half* __restrict__ uw_base,
    int mode)
{
    int e   = blockIdx.z;
    int cnt = mode ? T_TOK : g_cnt[e];
    int m0  = blockIdx.x * BM;
    if (m0 >= cnt) return;
    int n0  = blockIdx.y * 64;

    const int* tok = mode ? nullptr : (g_tok + e * T_TOK);
    __half* H = mode ? g_Hs : (g_H + (size_t)e * T_TOK * FDIM);
    const __half* gwe = gw_base + (size_t)e * FDIM * DIM;
    const __half* uwe = uw_base + (size_t)e * FDIM * DIM;

    extern __shared__ char smem[];
    uint32_t sb = smem_u32(smem);
    int tid  = threadIdx.x;
    int lane = tid & 31, wid = tid >> 5;
    int wm = wid & 1, wn = wid >> 1;

    const char* aSrc[2]; uint32_t aZ[2], aDst[2];
    const char* bSrc[2]; uint32_t bDst[2];
    #pragma unroll
    for (int j = 0; j < 2; j++) {
        int idx = tid + j * 256;
        int row = idx >> 2, seg = idx & 3;
        aDst[j] = (uint32_t)(row * (ASTRH * 2) + seg * 16);
        int grow = m0 + row;
        bool v = grow < cnt;
        int tk = v ? (tok ? tok[grow] : grow) : 0;
        aSrc[j] = (const char*)(xh + (size_t)tk * DIM + seg * 8);
        aZ[j] = v ? 16u : 0u;
        bDst[j] = (uint32_t)(A_BYTES + row * (ASTRH * 2) + seg * 16);
        bSrc[j] = (const char*)((row < 64 ? gwe + (size_t)(n0 + row) * DIM
                                          : uwe + (size_t)(n0 + row - 64) * DIM) + seg * 8);
    }

    // ldmatrix lane-invariant offsets (bytes)
    uint32_t aOff = (uint32_t)(((wm * 64 + (lane & 15)) * ASTRH + ((lane >> 4) * 8)) * 2);
    uint32_t bOff = (uint32_t)(A_BYTES +
        (((wn * 16) + ((lane >> 4) * 8) + (lane & 7)) * ASTRH + (((lane >> 3) & 1) * 8)) * 2);

    float cg[4][2][4] = {};
    float cu[4][2][4] = {};

    auto issue = [&](int k) {
        uint32_t base = sb + (uint32_t)(k & 3) * ST_BYTES;
        cpa16(base + aDst[0], aSrc[0] + (size_t)k * 64, aZ[0]);
        cpa16(base + aDst[1], aSrc[1] + (size_t)k * 64, aZ[1]);
        cpa16(base + bDst[0], bSrc[0] + (size_t)k * 64, 16u);
        cpa16(base + bDst[1], bSrc[1] + (size_t)k * 64, 16u);
        CP_COMMIT();
    };

    issue(0); issue(1); issue(2);
    const int KIT = DIM / BK;  // 32
    for (int k = 0; k < KIT; k++) {
        CP_WAIT2();
        __syncthreads();
        uint32_t bufA = sb + (uint32_t)(k & 3) * ST_BYTES + aOff;
        uint32_t bufB = sb + (uint32_t)(k & 3) * ST_BYTES + bOff;

        #pragma unroll
        for (int ks = 0; ks < 2; ks++) {
            uint32_t af[4][4];
            #pragma unroll
            for (int mi = 0; mi < 4; mi++)
                ldsm_x4(af[mi][0], af[mi][1], af[mi][2], af[mi][3],
                        bufA + (uint32_t)(mi * 16 * ASTRH * 2 + ks * 32));
            uint32_t bg[2][2], bu[2][2];
            ldsm_x4(bg[0][0], bg[0][1], bg[1][0], bg[1][1], bufB + (uint32_t)(ks * 32));
            ldsm_x4(bu[0][0], bu[0][1], bu[1][0], bu[1][1],
                    bufB + (uint32_t)(64 * ASTRH * 2 + ks * 32));
            #pragma unroll
            for (int mi = 0; mi < 4; mi++) {
                #pragma unroll
                for (int ni = 0; ni < 2; ni++) {
                    mma_f16(cg[mi][ni], af[mi], bg[ni]);
                    mma_f16(cu[mi][ni], af[mi], bu[ni]);
                }
            }
        }
        if (k + 3 < KIT) issue(k + 3); else CP_COMMIT();
    }

    #pragma unroll
    for (int mi = 0; mi < 4; mi++) {
        #pragma unroll
        for (int ni = 0; ni < 2; ni++) {
            int rbase = m0 + wm * 64 + mi * 16 + (lane >> 2);
            int cbase = n0 + wn * 16 + ni * 8 + (lane & 3) * 2;
            #pragma unroll
            for (int h = 0; h < 2; h++) {
                int row = rbase + h * 8;
                if (row < cnt) {
                    float g0 = cg[mi][ni][h * 2 + 0], g1 = cg[mi][ni][h * 2 + 1];
                    float u0 = cu[mi][ni][h * 2 + 0], u1 = cu[mi][ni][h * 2 + 1];
                    float h0 = g0 / (1.f + __expf(-g0)) * u0;
                    float h1 = g1 / (1.f + __expf(-g1)) * u1;
                    *(__half2*)(H + (size_t)row * FDIM + cbase) = __floats2half2_rn(h0, h1);
                }
            }
        }
    }
}

// ---------------- stage 2: Y = H @ down, fp16 mma + ldmatrix, BN=128 ---------
__global__ void __launch_bounds__(256, 2) ffn2_h(
    const __half* __restrict__ dw_base,
    int mode)
{
    int e   = blockIdx.z;
    int cnt = mode ? T_TOK : g_cnt[e];
    int m0  = blockIdx.x * BM;
    if (m0 >= cnt) return;
    int n0  = blockIdx.y * 128;

    const __half* A  = mode ? g_Hs : (g_H + (size_t)e * T_TOK * FDIM);
    const __half* dwe = dw_base + (size_t)e * DIM * FDIM;
    float* Y = mode ? g_Ys : (g_Yr + (size_t)e * T_TOK * DIM);

    extern __shared__ char smem[];
    uint32_t sb = smem_u32(smem);
    int tid  = threadIdx.x;
    int lane = tid & 31, wid = tid >> 5;
    int wm = wid & 1, wn = wid >> 1;

    const char* aSrc[2]; uint32_t aZ[2], aDst[2];
    const char* bSrc[2]; uint32_t bDst[2];
    #pragma unroll
    for (int j = 0; j < 2; j++) {
        int idx = tid + j * 256;
        int row = idx >> 2, seg = idx & 3;
        aDst[j] = (uint32_t)(row * (ASTRH * 2) + seg * 16);
        int grow = m0 + row;
        bool v = grow < cnt;
        aSrc[j] = (const char*)(A + (size_t)(v ? grow : 0) * FDIM + seg * 8);
        aZ[j] = v ? 16u : 0u;
        bDst[j] = (uint32_t)(A_BYTES + row * (ASTRH * 2) + seg * 16);
        bSrc[j] = (const char*)(dwe + (size_t)(n0 + row) * FDIM + seg * 8);
    }

    uint32_t aOff = (uint32_t)(((wm * 64 + (lane & 15)) * ASTRH + ((lane >> 4) * 8)) * 2);
    uint32_t bOff = (uint32_t)(A_BYTES +
        (((wn * 32) + ((lane >> 4) * 8) + (lane & 7)) * ASTRH + (((lane >> 3) & 1) * 8)) * 2);

    float cc_[4][4][4] = {};

    auto issue = [&](int k) {
        uint32_t base = sb + (uint32_t)(k & 3) * ST_BYTES;
        cpa16(base + aDst[0], aSrc[0] + (size_t)k * 64, aZ[0]);
        cpa16(base + aDst[1], aSrc[1] + (size_t)k * 64, aZ[1]);
        cpa16(base + bDst[0], bSrc[0] + (size_t)k * 64, 16u);
        cpa16(base + bDst[1], bSrc[1] + (size_t)k * 64, 16u);
        CP_COMMIT();
    };

    issue(0); issue(1); issue(2);
    const int KIT = FDIM / BK;  // 86
    for (int k = 0; k < KIT; k++) {
        CP_WAIT2();
        __syncthreads();
        uint32_t bufA = sb + (uint32_t)(k & 3) * ST_BYTES + aOff;
        uint32_t bufB = sb + (uint32_t)(k & 3) * ST_BYTES + bOff;

        #pragma unroll
        for (int ks = 0; ks < 2; ks++) {
            uint32_t af[4][4];
            #pragma unroll
            for (int mi = 0; mi < 4; mi++)
                ldsm_x4(af[mi][0], af[mi][1], af[mi][2], af[mi][3],
                        bufA + (uint32_t)(mi * 16 * ASTRH * 2 + ks * 32));
            uint32_t bf[4][2];
            ldsm_x4(bf[0][0], bf[0][1], bf[1][0], bf[1][1], bufB + (uint32_t)(ks * 32));
            ldsm_x4(bf[2][0], bf[2][1], bf[3][0], bf[3][1],
                    bufB + (uint32_t)(16 * ASTRH * 2 + ks * 32));
            #pragma unroll
            for (int mi = 0; mi < 4; mi++)
                #pragma unroll
                for (int ni = 0; ni < 4; ni++)
                    mma_f16(cc_[mi][ni], af[mi], bf[ni]);
        }
        if (k + 3 < KIT) issue(k + 3); else CP_COMMIT();
    }

    #pragma unroll
    for (int mi = 0; mi < 4; mi++) {
        #pragma unroll
        for (int ni = 0; ni < 4; ni++) {
            int rbase = m0 + wm * 64 + mi * 16 + (lane >> 2);
            int cbase = n0 + wn * 32 + ni * 8 + (lane & 3) * 2;
            #pragma unroll
            for (int h = 0; h < 2; h++) {
                int row = rbase + h * 8;
                if (row < cnt) {
                    Y[(size_t)row * DIM + cbase]     = cc_[mi][ni][h * 2 + 0];
                    Y[(size_t)row * DIM + cbase + 1] = cc_[mi][ni][h * 2 + 1];
                }
            }
        }
    }
}

// ---------------- combine ----------------------------------------------------
__global__ void combine_kernel(float* __restrict__ out) {
    int i  = blockIdx.x * blockDim.x + threadIdx.x;
    int t  = i / (DIM / 4);
    int dv = (i % (DIM / 4)) * 4;
    float w0 = g_cw[2 * t], w1 = g_cw[2 * t + 1];
    size_t s0 = (size_t)g_slot[2 * t] * DIM + dv;
    size_t s1 = (size_t)g_slot[2 * t + 1] * DIM + dv;
    float4 a = *(const float4*)(g_Yr + s0);
    float4 b = *(const float4*)(g_Yr + s1);
    float4 c = *(const float4*)(g_Ys + (size_t)t * DIM + dv);
    float4 o;
    o.x = w0 * a.x + w1 * b.x + c.x;
    o.y = w0 * a.y + w1 * b.y + c.y;
    o.z = w0 * a.z + w1 * b.z + c.z;
    o.w = w0 * a.w + w1 * b.w + c.w;
    *(float4*)(out + (size_t)t * DIM + dv) = o;
}

// ---------------- launch ------------------------------------------------------
extern "C" void kernel_launch(void* const* d_in, const int* in_sizes, int n_in,
                              void* d_out, int out_size) {
    const float* x   = (const float*)d_in[0];
    const float* rw  = (const float*)d_in[1];
    const float* rb  = (const float*)d_in[2];
    const float* gw  = (const float*)d_in[3];
    const float* uw  = (const float*)d_in[4];
    const float* dw  = (const float*)d_in[5];
    const float* sgw = (const float*)d_in[6];
    const float* suw = (const float*)d_in[7];
    const float* sdw = (const float*)d_in[8];
    float* out = (float*)d_out;

    cudaFuncSetAttribute(ffn1_h, cudaFuncAttributeMaxDynamicSharedMemorySize, SMEM_SZ);
    cudaFuncSetAttribute(ffn2_h, cudaFuncAttributeMaxDynamicSharedMemorySize, SMEM_SZ);

    __half *xh, *gwH, *uwH, *dwH, *sgwH, *suwH, *sdwH;
    cudaGetSymbolAddress((void**)&xh,   g_xH);
    cudaGetSymbolAddress((void**)&gwH,  g_gwH);
    cudaGetSymbolAddress((void**)&uwH,  g_uwH);
    cudaGetSymbolAddress((void**)&dwH,  g_dwH);
    cudaGetSymbolAddress((void**)&sgwH, g_sgwH);
    cudaGetSymbolAddress((void**)&suwH, g_suwH);
    cudaGetSymbolAddress((void**)&sdwH, g_sdwH);

    dim3 tb(32, 8);

    cvtx_zero_kernel<<<(T_TOK * DIM) / 1024, 256>>>(x, xh);                       // 1
    router_kernel<<<T_TOK / 8, 256>>>(x, rw, rb);                                 // 2
    cvt_trans<<<dim3(DIM/32, FDIM/32, 2*NEXP), tb>>>(gw, uw, gwH, uwH,
                                                     DIM, FDIM, 1);               // 3
    dim3 g1(T_TOK / BM, FDIM / 64, NEXP);
    ffn1_h<<<g1, 256, SMEM_SZ>>>(xh, gwH, uwH, 0);                                // 4 <- profiled
    cvt_trans<<<dim3(DIM/32, FDIM/32, 2), tb>>>(sgw, suw, sgwH, suwH,
                                                DIM, FDIM, 1);                    // 5
    dim3 g1s(T_TOK / BM, FDIM / 64, 1);
    ffn1_h<<<g1s, 256, SMEM_SZ>>>(xh, sgwH, suwH, 1);                             // 6
    cvt_trans<<<dim3(FDIM/32, DIM/32, NEXP), tb>>>(dw, dw, dwH, dwH,
                                                   FDIM, DIM, 0);                 // 7
    dim3 g2(T_TOK / BM, DIM / 128, NEXP);
    ffn2_h<<<g2, 256, SMEM_SZ>>>(dwH, 0);                                         // 8
    cvt_trans<<<dim3(FDIM/32, DIM/32, 1), tb>>>(sdw, sdw, sdwH, sdwH,
                                                FDIM, DIM, 0);                    // 9
    dim3 g2s(T_TOK / BM, DIM / 128, 1);
    ffn2_h<<<g2s, 256, SMEM_SZ>>>(sdwH, 1);                                       // 10
    combine_kernel<<<(T_TOK * (DIM / 4)) / 256, 256>>>(out);                      // 11
}

// round 7
// speedup vs baseline: 2.8463x; 1.0733x over previous
#include <cuda_runtime.h>
#include <cuda_fp16.h>
#include <cstdint>
#include <cstddef>

#define T_TOK 8192
#define DIM   1024
#define FDIM  2752
#define NEXP  8

#define BM 128
#define BK 32
#define ASTRH 40                       // A smem row: 32 halves + 8 pad
#define A_BYTES (BM * ASTRH * 2)       // 10240
// ffn1 B: k-major tile [32 k][64 n + 8 pad] per matrix
#define B1STRB 144                     // (64+8)*2 bytes per k-row
#define B1_BYTES (BK * B1STRB)         // 4608
#define ST1_BYTES (A_BYTES + 2 * B1_BYTES) // 19456
#define SMEM1 (4 * ST1_BYTES)          // 77824
// ffn2 B: [32 k][128 n + 8 pad]
#define B2STRB 272
#define B2_BYTES (BK * B2STRB)         // 8704
#define ST2_BYTES (A_BYTES + B2_BYTES) // 18944
#define SMEM2 (4 * ST2_BYTES)          // 75776

// ---------------- scratch ----------------------------------------------------
__device__ int    g_cnt[NEXP];
__device__ int    g_tok[NEXP * T_TOK];
__device__ int    g_slot[T_TOK * 2];
__device__ float  g_cw[T_TOK * 2];
__device__ __half g_xH [(size_t)T_TOK * DIM];
__device__ __half g_gwH[(size_t)NEXP * DIM * FDIM];   // ORIGINAL [D][F] layout, fp16
__device__ __half g_uwH[(size_t)NEXP * DIM * FDIM];
__device__ __half g_dwH[(size_t)NEXP * FDIM * DIM];   // ORIGINAL [F][D]
__device__ __half g_sgwH[(size_t)DIM * FDIM];
__device__ __half g_suwH[(size_t)DIM * FDIM];
__device__ __half g_sdwH[(size_t)FDIM * DIM];
__device__ __half g_H  [(size_t)NEXP * T_TOK * FDIM];
__device__ __half g_Hs [(size_t)T_TOK * FDIM];
__device__ float  g_Yr [(size_t)NEXP * T_TOK * DIM];
__device__ float  g_Ys [(size_t)T_TOK * DIM];

// ---------------- helpers ----------------------------------------------------
__device__ __forceinline__ uint32_t smem_u32(const void* p) {
    uint32_t a;
    asm("{ .reg .u64 t; cvta.to.shared.u64 t, %1; cvt.u32.u64 %0, t; }" : "=r"(a) : "l"(p));
    return a;
}
__device__ __forceinline__ void cpa16(uint32_t dst, const void* src, uint32_t nbytes) {
    asm volatile("cp.async.cg.shared.global [%0], [%1], 16, %2;"
                 :: "r"(dst), "l"(src), "r"(nbytes) : "memory");
}
#define CP_COMMIT() asm volatile("cp.async.commit_group;" ::: "memory")
#define CP_WAIT2()  asm volatile("cp.async.wait_group 2;" ::: "memory")

__device__ __forceinline__ void mma_f16(float* c, const uint32_t* a, const uint32_t* b) {
    asm volatile(
        "mma.sync.aligned.m16n8k16.row.col.f32.f16.f16.f32 "
        "{%0,%1,%2,%3}, {%4,%5,%6,%7}, {%8,%9}, {%0,%1,%2,%3};\n"
        : "+f"(c[0]), "+f"(c[1]), "+f"(c[2]), "+f"(c[3])
        : "r"(a[0]), "r"(a[1]), "r"(a[2]), "r"(a[3]),
          "r"(b[0]), "r"(b[1]));
}
__device__ __forceinline__ void ldsm_x4(uint32_t& r0, uint32_t& r1, uint32_t& r2,
                                        uint32_t& r3, uint32_t a) {
    asm volatile("ldmatrix.sync.aligned.m8n8.x4.shared.b16 {%0,%1,%2,%3}, [%4];"
                 : "=r"(r0), "=r"(r1), "=r"(r2), "=r"(r3) : "r"(a));
}
__device__ __forceinline__ void ldsm_x4t(uint32_t& r0, uint32_t& r1, uint32_t& r2,
                                         uint32_t& r3, uint32_t a) {
    asm volatile("ldmatrix.sync.aligned.m8n8.x4.trans.shared.b16 {%0,%1,%2,%3}, [%4];"
                 : "=r"(r0), "=r"(r1), "=r"(r2), "=r"(r3) : "r"(a));
}

// ---------------- prep kernels ------------------------------------------------
__global__ void cvtx_zero_kernel(const float* __restrict__ x, __half* __restrict__ xh) {
    if (blockIdx.x == 0 && threadIdx.x < NEXP) g_cnt[threadIdx.x] = 0;
    size_t i = ((size_t)blockIdx.x * 256 + threadIdx.x) * 4;
    float4 v = *(const float4*)(x + i);
    __half2* o = (__half2*)(xh + i);
    o[0] = __floats2half2_rn(v.x, v.y);
    o[1] = __floats2half2_rn(v.z, v.w);
}

// streaming fp32 -> fp16 convert for two equal-size buffers (no transpose)
__global__ void cvt2_kernel(const float* __restrict__ s0, const float* __restrict__ s1,
                            __half* __restrict__ d0, __half* __restrict__ d1,
                            size_t nquads) {
    size_t i = (size_t)blockIdx.x * 256 + threadIdx.x;
    const float* s; __half* d;
    if (i < nquads) { s = s0; d = d0; } else { s = s1; d = d1; i -= nquads; }
    float4 v = *(const float4*)(s + i * 4);
    __half2* o = (__half2*)(d + i * 4);
    o[0] = __floats2half2_rn(v.x, v.y);
    o[1] = __floats2half2_rn(v.z, v.w);
}

// ---------------- router -----------------------------------------------------
__global__ void router_kernel(const float* __restrict__ x,
                              const float* __restrict__ rw,
                              const float* __restrict__ rb) {
    int wid = threadIdx.x >> 5, lane = threadIdx.x & 31;
    int t = blockIdx.x * 8 + wid;
    if (t >= T_TOK) return;
    const float* xrow = x + (size_t)t * DIM;
    float lg[NEXP] = {0.f,0.f,0.f,0.f,0.f,0.f,0.f,0.f};
    for (int j = lane; j < DIM; j += 32) {
        float xv = xrow[j];
        const float* w = rw + (size_t)j * NEXP;
        #pragma unroll
        for (int e = 0; e < NEXP; e++) lg[e] += xv * w[e];
    }
    #pragma unroll
    for (int e = 0; e < NEXP; e++)
        #pragma unroll
        for (int o = 16; o > 0; o >>= 1)
            lg[e] += __shfl_xor_sync(0xffffffffu, lg[e], o);
    if (lane == 0) {
        float p[NEXP];
        #pragma unroll
        for (int e = 0; e < NEXP; e++) lg[e] += rb[e];
        float m = lg[0];
        #pragma unroll
        for (int e = 1; e < NEXP; e++) m = fmaxf(m, lg[e]);
        float s = 0.f;
        #pragma unroll
        for (int e = 0; e < NEXP; e++) { p[e] = __expf(lg[e] - m); s += p[e]; }
        #pragma unroll
        for (int e = 0; e < NEXP; e++) p[e] /= s;
        int e0 = 0;
        #pragma unroll
        for (int e = 1; e < NEXP; e++) if (p[e] > p[e0]) e0 = e;
        int e1 = (e0 == 0) ? 1 : 0;
        #pragma unroll
        for (int e = 0; e < NEXP; e++) if (e != e0 && p[e] > p[e1]) e1 = e;
        float den = p[e0] + p[e1] + 1e-20f;
        int pos0 = atomicAdd(&g_cnt[e0], 1);
        g_tok[e0 * T_TOK + pos0] = t;
        g_slot[2 * t]     = e0 * T_TOK + pos0;
        g_cw[2 * t]       = p[e0] / den;
        int pos1 = atomicAdd(&g_cnt[e1], 1);
        g_tok[e1 * T_TOK + pos1] = t;
        g_slot[2 * t + 1] = e1 * T_TOK + pos1;
        g_cw[2 * t + 1]   = p[e1] / den;
    }
}

// ---------------- stage 1: H = silu(X@G)*(X@U) -------------------------------
// weights k-major [D][F]; B loaded with ldmatrix.trans
__global__ void __launch_bounds__(256, 2) ffn1_h(
    const __half* __restrict__ xh,
    const __half* __restrict__ gw_base,
    const __half* __restrict__ uw_base,
    int mode)
{
    int e   = blockIdx.z;
    int cnt = mode ? T_TOK : g_cnt[e];
    int m0  = blockIdx.x * BM;
    if (m0 >= cnt) return;
    int n0  = blockIdx.y * 64;

    const int* tok = mode ? nullptr : (g_tok + e * T_TOK);
    __half* H = mode ? g_Hs : (g_H + (size_t)e * T_TOK * FDIM);
    const __half* gwe = gw_base + (size_t)e * DIM * FDIM;
    const __half* uwe = uw_base + (size_t)e * DIM * FDIM;

    extern __shared__ char smem[];
    uint32_t sb = smem_u32(smem);
    int tid  = threadIdx.x;
    int lane = tid & 31, wid = tid >> 5;
    int wm = wid & 1, wn = wid >> 1;

    // A loads: 2 x 16B per thread
    const char* aSrc[2]; uint32_t aZ[2], aDst[2];
    #pragma unroll
    for (int j = 0; j < 2; j++) {
        int idx = tid + j * 256;
        int row = idx >> 2, seg = idx & 3;
        aDst[j] = (uint32_t)(row * (ASTRH * 2) + seg * 16);
        int grow = m0 + row;
        bool v = grow < cnt;
        int tk = v ? (tok ? tok[grow] : grow) : 0;
        aSrc[j] = (const char*)(xh + (size_t)tk * DIM + seg * 8);
        aZ[j] = v ? 16u : 0u;
    }
    // B loads (k-major): 32 k-rows x 64 n-cols per matrix; 1 x 16B per thread per matrix
    int brow = tid >> 3, bseg = tid & 7;
    uint32_t bDstG = (uint32_t)(A_BYTES + brow * B1STRB + bseg * 16);
    const char* bSrcG = (const char*)(gwe + (size_t)brow * FDIM + n0 + bseg * 8);
    const char* bSrcU = (const char*)(uwe + (size_t)brow * FDIM + n0 + bseg * 8);

    // ldmatrix offsets
    uint32_t aOff = (uint32_t)(((wm * 64 + (lane & 15)) * ASTRH + ((lane >> 4) * 8)) * 2);
    uint32_t bOff = (uint32_t)(A_BYTES + (lane & 15) * B1STRB +
                               (wn * 16 + ((lane >> 4) * 8)) * 2);

    float cg[4][2][4] = {};
    float cu[4][2][4] = {};

    auto issue = [&](int k) {
        uint32_t base = sb + (uint32_t)(k & 3) * ST1_BYTES;
        size_t bo = (size_t)k * (BK * FDIM * 2);
        cpa16(base + aDst[0], aSrc[0] + (size_t)k * 64, aZ[0]);
        cpa16(base + aDst[1], aSrc[1] + (size_t)k * 64, aZ[1]);
        cpa16(base + bDstG,            bSrcG + bo, 16u);
        cpa16(base + B1_BYTES + bDstG, bSrcU + bo, 16u);
        CP_COMMIT();
    };

    issue(0); issue(1); issue(2);
    const int KIT = DIM / BK;  // 32
    for (int k = 0; k < KIT; k++) {
        CP_WAIT2();
        __syncthreads();
        uint32_t bufA = sb + (uint32_t)(k & 3) * ST1_BYTES + aOff;
        uint32_t bufB = sb + (uint32_t)(k & 3) * ST1_BYTES + bOff;

        #pragma unroll
        for (int ks = 0; ks < 2; ks++) {
            uint32_t af[4][4];
            #pragma unroll
            for (int mi = 0; mi < 4; mi++)
                ldsm_x4(af[mi][0], af[mi][1], af[mi][2], af[mi][3],
                        bufA + (uint32_t)(mi * 16 * ASTRH * 2 + ks * 32));
            uint32_t bg[2][2], bu[2][2];
            uint32_t bt = bufB + (uint32_t)(ks * 16 * B1STRB);
            ldsm_x4t(bg[0][0], bg[0][1], bg[1][0], bg[1][1], bt);
            ldsm_x4t(bu[0][0], bu[0][1], bu[1][0], bu[1][1], bt + B1_BYTES);
            #pragma unroll
            for (int mi = 0; mi < 4; mi++) {
                #pragma unroll
                for (int ni = 0; ni < 2; ni++) {
                    mma_f16(cg[mi][ni], af[mi], bg[ni]);
                    mma_f16(cu[mi][ni], af[mi], bu[ni]);
                }
            }
        }
        if (k + 3 < KIT) issue(k + 3); else CP_COMMIT();
    }

    #pragma unroll
    for (int mi = 0; mi < 4; mi++) {
        #pragma unroll
        for (int ni = 0; ni < 2; ni++) {
            int rbase = m0 + wm * 64 + mi * 16 + (lane >> 2);
            int cbase = n0 + wn * 16 + ni * 8 + (lane & 3) * 2;
            #pragma unroll
            for (int h = 0; h < 2; h++) {
                int row = rbase + h * 8;
                if (row < cnt) {
                    float g0 = cg[mi][ni][h * 2 + 0], g1 = cg[mi][ni][h * 2 + 1];
                    float u0 = cu[mi][ni][h * 2 + 0], u1 = cu[mi][ni][h * 2 + 1];
                    float h0 = g0 / (1.f + __expf(-g0)) * u0;
                    float h1 = g1 / (1.f + __expf(-g1)) * u1;
                    *(__half2*)(H + (size_t)row * FDIM + cbase) = __floats2half2_rn(h0, h1);
                }
            }
        }
    }
}

// ---------------- stage 2: Y = H @ down, BN=128 ------------------------------
// dw k-major [F][D]; B via ldmatrix.trans
__global__ void __launch_bounds__(256, 2) ffn2_h(
    const __half* __restrict__ dw_base,
    int mode)
{
    int e   = blockIdx.z;
    int cnt = mode ? T_TOK : g_cnt[e];
    int m0  = blockIdx.x * BM;
    if (m0 >= cnt) return;
    int n0  = blockIdx.y * 128;

    const __half* A  = mode ? g_Hs : (g_H + (size_t)e * T_TOK * FDIM);
    const __half* dwe = dw_base + (size_t)e * FDIM * DIM;
    float* Y = mode ? g_Ys : (g_Yr + (size_t)e * T_TOK * DIM);

    extern __shared__ char smem[];
    uint32_t sb = smem_u32(smem);
    int tid  = threadIdx.x;
    int lane = tid & 31, wid = tid >> 5;
    int wm = wid & 1, wn = wid >> 1;

    const char* aSrc[2]; uint32_t aZ[2], aDst[2];
    const char* bSrc[2]; uint32_t bDst[2];
    #pragma unroll
    for (int j = 0; j < 2; j++) {
        int idx = tid + j * 256;
        int row = idx >> 2, seg = idx & 3;
        aDst[j] = (uint32_t)(row * (ASTRH * 2) + seg * 16);
        int grow = m0 + row;
        bool v = grow < cnt;
        aSrc[j] = (const char*)(A + (size_t)(v ? grow : 0) * FDIM + seg * 8);
        aZ[j] = v ? 16u : 0u;
        int brow = idx >> 4, bseg = idx & 15;
        bDst[j] = (uint32_t)(A_BYTES + brow * B2STRB + bseg * 16);
        bSrc[j] = (const char*)(dwe + (size_t)brow * DIM + n0 + bseg * 8);
    }

    uint32_t aOff = (uint32_t)(((wm * 64 + (lane & 15)) * ASTRH + ((lane >> 4) * 8)) * 2);
    uint32_t bOff = (uint32_t)(A_BYTES + (lane & 15) * B2STRB +
                               (wn * 32 + ((lane >> 4) * 8)) * 2);

    float cc_[4][4][4] = {};

    auto issue = [&](int k) {
        uint32_t base = sb + (uint32_t)(k & 3) * ST2_BYTES;
        size_t bo = (size_t)k * (BK * DIM * 2);
        cpa16(base + aDst[0], aSrc[0] + (size_t)k * 64, aZ[0]);
        cpa16(base + aDst[1], aSrc[1] + (size_t)k * 64, aZ[1]);
        cpa16(base + bDst[0], bSrc[0] + bo, 16u);
        cpa16(base + bDst[1], bSrc[1] + bo, 16u);
        CP_COMMIT();
    };

    issue(0); issue(1); issue(2);
    const int KIT = FDIM / BK;  // 86
    for (int k = 0; k < KIT; k++) {
        CP_WAIT2();
        __syncthreads();
        uint32_t bufA = sb + (uint32_t)(k & 3) * ST2_BYTES + aOff;
        uint32_t bufB = sb + (uint32_t)(k & 3) * ST2_BYTES + bOff;

        #pragma unroll
        for (int ks = 0; ks < 2; ks++) {
            uint32_t af[4][4];
            #pragma unroll
            for (int mi = 0; mi < 4; mi++)
                ldsm_x4(af[mi][0], af[mi][1], af[mi][2], af[mi][3],
                        bufA + (uint32_t)(mi * 16 * ASTRH * 2 + ks * 32));
            uint32_t bf[4][2];
            uint32_t bt = bufB + (uint32_t)(ks * 16 * B2STRB);
            ldsm_x4t(bf[0][0], bf[0][1], bf[1][0], bf[1][1], bt);
            ldsm_x4t(bf[2][0], bf[2][1], bf[3][0], bf[3][1], bt + 32);
            #pragma unroll
            for (int mi = 0; mi < 4; mi++)
                #pragma unroll
                for (int ni = 0; ni < 4; ni++)
                    mma_f16(cc_[mi][ni], af[mi], bf[ni]);
        }
        if (k + 3 < KIT) issue(k + 3); else CP_COMMIT();
    }

    #pragma unroll
    for (int mi = 0; mi < 4; mi++) {
        #pragma unroll
        for (int ni = 0; ni < 4; ni++) {
            int rbase = m0 + wm * 64 + mi * 16 + (lane >> 2);
            int cbase = n0 + wn * 32 + ni * 8 + (lane & 3) * 2;
            #pragma unroll
            for (int h = 0; h < 2; h++) {
                int row = rbase + h * 8;
                if (row < cnt) {
                    Y[(size_t)row * DIM + cbase]     = cc_[mi][ni][h * 2 + 0];
                    Y[(size_t)row * DIM + cbase + 1] = cc_[mi][ni][h * 2 + 1];
                }
            }
        }
    }
}

// ---------------- combine ----------------------------------------------------
__global__ void combine_kernel(float* __restrict__ out) {
    int i  = blockIdx.x * blockDim.x + threadIdx.x;
    int t  = i / (DIM / 4);
    int dv = (i % (DIM / 4)) * 4;
    float w0 = g_cw[2 * t], w1 = g_cw[2 * t + 1];
    size_t s0 = (size_t)g_slot[2 * t] * DIM + dv;
    size_t s1 = (size_t)g_slot[2 * t + 1] * DIM + dv;
    float4 a = *(const float4*)(g_Yr + s0);
    float4 b = *(const float4*)(g_Yr + s1);
    float4 c = *(const float4*)(g_Ys + (size_t)t * DIM + dv);
    float4 o;
    o.x = w0 * a.x + w1 * b.x + c.x;
    o.y = w0 * a.y + w1 * b.y + c.y;
    o.z = w0 * a.z + w1 * b.z + c.z;
    o.w = w0 * a.w + w1 * b.w + c.w;
    *(float4*)(out + (size_t)t * DIM + dv) = o;
}

// ---------------- launch ------------------------------------------------------
extern "C" void kernel_launch(void* const* d_in, const int* in_sizes, int n_in,
                              void* d_out, int out_size) {
    const float* x   = (const float*)d_in[0];
    const float* rw  = (const float*)d_in[1];
    const float* rb  = (const float*)d_in[2];
    const float* gw  = (const float*)d_in[3];
    const float* uw  = (const float*)d_in[4];
    const float* dw  = (const float*)d_in[5];
    const float* sgw = (const float*)d_in[6];
    const float* suw = (const float*)d_in[7];
    const float* sdw = (const float*)d_in[8];
    float* out = (float*)d_out;

    cudaFuncSetAttribute(ffn1_h, cudaFuncAttributeMaxDynamicSharedMemorySize, SMEM1);
    cudaFuncSetAttribute(ffn2_h, cudaFuncAttributeMaxDynamicSharedMemorySize, SMEM2);

    __half *xh, *gwH, *uwH, *dwH, *sgwH, *suwH, *sdwH;
    cudaGetSymbolAddress((void**)&xh,   g_xH);
    cudaGetSymbolAddress((void**)&gwH,  g_gwH);
    cudaGetSymbolAddress((void**)&uwH,  g_uwH);
    cudaGetSymbolAddress((void**)&dwH,  g_dwH);
    cudaGetSymbolAddress((void**)&sgwH, g_sgwH);
    cudaGetSymbolAddress((void**)&suwH, g_suwH);
    cudaGetSymbolAddress((void**)&sdwH, g_sdwH);

    const size_t WQ  = (size_t)NEXP * DIM * FDIM / 4;  // quads per routed weight
    const size_t SWQ = (size_t)DIM * FDIM / 4;         // quads per shared weight

    cvtx_zero_kernel<<<(T_TOK * DIM) / 1024, 256>>>(x, xh);                       // 1
    router_kernel<<<T_TOK / 8, 256>>>(x, rw, rb);                                 // 2
    cvt2_kernel<<<(int)(2 * WQ / 256), 256>>>(gw, uw, gwH, uwH, WQ);              // 3
    dim3 g1(T_TOK / BM, FDIM / 64, NEXP);
    ffn1_h<<<g1, 256, SMEM1>>>(xh, gwH, uwH, 0);                                  // 4 <- profiled
    cvt2_kernel<<<(int)(2 * SWQ / 256), 256>>>(sgw, suw, sgwH, suwH, SWQ);        // 5
    dim3 g1s(T_TOK / BM, FDIM / 64, 1);
    ffn1_h<<<g1s, 256, SMEM1>>>(xh, sgwH, suwH, 1);                               // 6
    cvt2_kernel<<<(int)(2 * (WQ / 2) / 256), 256>>>(dw, dw + WQ * 2, dwH,
                                                    dwH + WQ * 2, WQ / 2);        // 7
    dim3 g2(T_TOK / BM, DIM / 128, NEXP);
    ffn2_h<<<g2, 256, SMEM2>>>(dwH, 0);                                           // 8
    cvt2_kernel<<<(int)(2 * (SWQ / 2) / 256), 256>>>(sdw, sdw + SWQ * 2, sdwH,
                                                     sdwH + SWQ * 2, SWQ / 2);    // 9
    dim3 g2s(T_TOK / BM, DIM / 128, 1);
    ffn2_h<<<g2s, 256, SMEM2>>>(sdwH, 1);                                         // 10
    combine_kernel<<<(T_TOK * (DIM / 4)) / 256, 256>>>(out);                      // 11
}

// round 8
// speedup vs baseline: 3.1533x; 1.1079x over previous
#include <cuda_runtime.h>
#include <cuda_fp16.h>
#include <cstdint>
#include <cstddef>

#define T_TOK 8192
#define DIM   1024
#define FDIM  2752
#define NEXP  8

#define BM 128
#define BK 32
// swizzled, pad-free tiles
#define A_SZ   8192                   // 128 rows x 64B
#define ST_SZ  16384                  // A + B (8192 each) for both kernels
#define NSTG   6
#define SMEM_SZ (NSTG * ST_SZ)        // 98304

// ---------------- scratch ----------------------------------------------------
__device__ int    g_cnt[NEXP];
__device__ int    g_tok[NEXP * T_TOK];
__device__ int    g_slot[T_TOK * 2];
__device__ float  g_cw[T_TOK * 2];
__device__ __half g_xH [(size_t)T_TOK * DIM];
__device__ __half g_gwH[(size_t)NEXP * DIM * FDIM];   // original [D][F], fp16
__device__ __half g_uwH[(size_t)NEXP * DIM * FDIM];
__device__ __half g_dwH[(size_t)NEXP * FDIM * DIM];   // original [F][D]
__device__ __half g_sgwH[(size_t)DIM * FDIM];
__device__ __half g_suwH[(size_t)DIM * FDIM];
__device__ __half g_sdwH[(size_t)FDIM * DIM];
__device__ __half g_H  [(size_t)NEXP * T_TOK * FDIM];
__device__ __half g_Hs [(size_t)T_TOK * FDIM];
__device__ float  g_Yr [(size_t)NEXP * T_TOK * DIM];
__device__ float  g_Ys [(size_t)T_TOK * DIM];

// ---------------- helpers ----------------------------------------------------
__device__ __forceinline__ uint32_t smem_u32(const void* p) {
    uint32_t a;
    asm("{ .reg .u64 t; cvta.to.shared.u64 t, %1; cvt.u32.u64 %0, t; }" : "=r"(a) : "l"(p));
    return a;
}
__device__ __forceinline__ void cpa16(uint32_t dst, const void* src, uint32_t nbytes) {
    asm volatile("cp.async.cg.shared.global [%0], [%1], 16, %2;"
                 :: "r"(dst), "l"(src), "r"(nbytes) : "memory");
}
#define CP_COMMIT() asm volatile("cp.async.commit_group;" ::: "memory")
#define CP_WAIT2()  asm volatile("cp.async.wait_group 2;" ::: "memory")

__device__ __forceinline__ void mma_f16(float* c, const uint32_t* a, const uint32_t* b) {
    asm volatile(
        "mma.sync.aligned.m16n8k16.row.col.f32.f16.f16.f32 "
        "{%0,%1,%2,%3}, {%4,%5,%6,%7}, {%8,%9}, {%0,%1,%2,%3};\n"
        : "+f"(c[0]), "+f"(c[1]), "+f"(c[2]), "+f"(c[3])
        : "r"(a[0]), "r"(a[1]), "r"(a[2]), "r"(a[3]),
          "r"(b[0]), "r"(b[1]));
}
__device__ __forceinline__ void ldsm_x4(uint32_t& r0, uint32_t& r1, uint32_t& r2,
                                        uint32_t& r3, uint32_t a) {
    asm volatile("ldmatrix.sync.aligned.m8n8.x4.shared.b16 {%0,%1,%2,%3}, [%4];"
                 : "=r"(r0), "=r"(r1), "=r"(r2), "=r"(r3) : "r"(a));
}
__device__ __forceinline__ void ldsm_x4t(uint32_t& r0, uint32_t& r1, uint32_t& r2,
                                         uint32_t& r3, uint32_t a) {
    asm volatile("ldmatrix.sync.aligned.m8n8.x4.trans.shared.b16 {%0,%1,%2,%3}, [%4];"
                 : "=r"(r0), "=r"(r1), "=r"(r2), "=r"(r3) : "r"(a));
}

// ---------------- prep kernels ------------------------------------------------
__global__ void cvtx_zero_kernel(const float* __restrict__ x, __half* __restrict__ xh) {
    if (blockIdx.x == 0 && threadIdx.x < NEXP) g_cnt[threadIdx.x] = 0;
    size_t i = ((size_t)blockIdx.x * 256 + threadIdx.x) * 4;
    float4 v = *(const float4*)(x + i);
    __half2* o = (__half2*)(xh + i);
    o[0] = __floats2half2_rn(v.x, v.y);
    o[1] = __floats2half2_rn(v.z, v.w);
}

__global__ void cvt2_kernel(const float* __restrict__ s0, const float* __restrict__ s1,
                            __half* __restrict__ d0, __half* __restrict__ d1,
                            size_t nquads) {
    size_t i = (size_t)blockIdx.x * 256 + threadIdx.x;
    const float* s; __half* d;
    if (i < nquads) { s = s0; d = d0; } else { s = s1; d = d1; i -= nquads; }
    float4 v = *(const float4*)(s + i * 4);
    __half2* o = (__half2*)(d + i * 4);
    o[0] = __floats2half2_rn(v.x, v.y);
    o[1] = __floats2half2_rn(v.z, v.w);
}

// ---------------- router -----------------------------------------------------
__global__ void router_kernel(const float* __restrict__ x,
                              const float* __restrict__ rw,
                              const float* __restrict__ rb) {
    int wid = threadIdx.x >> 5, lane = threadIdx.x & 31;
    int t = blockIdx.x * 8 + wid;
    if (t >= T_TOK) return;
    const float* xrow = x + (size_t)t * DIM;
    float lg[NEXP] = {0.f,0.f,0.f,0.f,0.f,0.f,0.f,0.f};
    for (int j = lane; j < DIM; j += 32) {
        float xv = xrow[j];
        const float* w = rw + (size_t)j * NEXP;
        #pragma unroll
        for (int e = 0; e < NEXP; e++) lg[e] += xv * w[e];
    }
    #pragma unroll
    for (int e = 0; e < NEXP; e++)
        #pragma unroll
        for (int o = 16; o > 0; o >>= 1)
            lg[e] += __shfl_xor_sync(0xffffffffu, lg[e], o);
    if (lane == 0) {
        float p[NEXP];
        #pragma unroll
        for (int e = 0; e < NEXP; e++) lg[e] += rb[e];
        float m = lg[0];
        #pragma unroll
        for (int e = 1; e < NEXP; e++) m = fmaxf(m, lg[e]);
        float s = 0.f;
        #pragma unroll
        for (int e = 0; e < NEXP; e++) { p[e] = __expf(lg[e] - m); s += p[e]; }
        #pragma unroll
        for (int e = 0; e < NEXP; e++) p[e] /= s;
        int e0 = 0;
        #pragma unroll
        for (int e = 1; e < NEXP; e++) if (p[e] > p[e0]) e0 = e;
        int e1 = (e0 == 0) ? 1 : 0;
        #pragma unroll
        for (int e = 0; e < NEXP; e++) if (e != e0 && p[e] > p[e1]) e1 = e;
        float den = p[e0] + p[e1] + 1e-20f;
        int pos0 = atomicAdd(&g_cnt[e0], 1);
        g_tok[e0 * T_TOK + pos0] = t;
        g_slot[2 * t]     = e0 * T_TOK + pos0;
        g_cw[2 * t]       = p[e0] / den;
        int pos1 = atomicAdd(&g_cnt[e1], 1);
        g_tok[e1 * T_TOK + pos1] = t;
        g_slot[2 * t + 1] = e1 * T_TOK + pos1;
        g_cw[2 * t + 1]   = p[e1] / den;
    }
}

// ---------------- stage 1: H = silu(X@G)*(X@U) -------------------------------
__global__ void __launch_bounds__(256, 2) ffn1_h(
    const __half* __restrict__ xh,
    const __half* __restrict__ gw_base,
    const __half* __restrict__ uw_base,
    int mode)
{
    int e   = blockIdx.z;
    int cnt = mode ? T_TOK : g_cnt[e];
    int m0  = blockIdx.x * BM;
    if (m0 >= cnt) return;
    int n0  = blockIdx.y * 64;

    const int* tok = mode ? nullptr : (g_tok + e * T_TOK);
    __half* H = mode ? g_Hs : (g_H + (size_t)e * T_TOK * FDIM);
    const __half* gwe = gw_base + (size_t)e * DIM * FDIM;
    const __half* uwe = uw_base + (size_t)e * DIM * FDIM;

    extern __shared__ char smem[];
    uint32_t sb = smem_u32(smem);
    int tid  = threadIdx.x;
    int lane = tid & 31, wid = tid >> 5;
    int wm = wid & 1, wn = wid >> 1;   // wn: 0..3 (16-col slice)

    // A stores: 2 x 16B per thread, swizzled chunk = seg ^ ((row>>1)&3)
    const char* aSrc[2]; uint32_t aZ[2], aDst[2];
    #pragma unroll
    for (int j = 0; j < 2; j++) {
        int idx = tid + j * 256;
        int row = idx >> 2, seg = idx & 3;
        aDst[j] = (uint32_t)(row * 64 + ((seg ^ ((row >> 1) & 3)) << 4));
        int grow = m0 + row;
        bool v = grow < cnt;
        int tk = v ? (tok ? tok[grow] : grow) : 0;
        aSrc[j] = (const char*)(xh + (size_t)tk * DIM + seg * 8);
        aZ[j] = v ? 16u : 0u;
    }
    // B stores (k-major): 32 rows x 128B per matrix; chunk = bseg ^ (brow&7)
    int brow = tid >> 3, bseg = tid & 7;
    uint32_t bDstG = (uint32_t)(A_SZ + brow * 128 + ((bseg ^ (brow & 7)) << 4));
    const char* bSrcG = (const char*)(gwe + (size_t)brow * FDIM + n0 + bseg * 8);
    const char* bSrcU = (const char*)(uwe + (size_t)brow * FDIM + n0 + bseg * 8);

    // per-lane read constants
    int hi = lane >> 4, lrow = lane & 15;
    uint32_t aRow = (uint32_t)((wm * 64 + lrow) * 64);
    uint32_t swA  = (uint32_t)((lrow >> 1) & 3);
    uint32_t bRow = (uint32_t)(A_SZ + lrow * 128);
    uint32_t swB  = (uint32_t)(lrow & 7);
    uint32_t cB   = ((uint32_t)(wn * 2 + hi) ^ swB) << 4;   // ks-invariant

    float cg[4][2][4] = {};
    float cu[4][2][4] = {};

    auto issue = [&](int k) {
        uint32_t base = sb + (uint32_t)(k % NSTG) * ST_SZ;
        size_t ao = (size_t)k * 64;
        size_t bo = (size_t)k * (BK * FDIM * 2);
        cpa16(base + aDst[0], aSrc[0] + ao, aZ[0]);
        cpa16(base + aDst[1], aSrc[1] + ao, aZ[1]);
        cpa16(base + bDstG,        bSrcG + bo, 16u);
        cpa16(base + bDstG + 4096, bSrcU + bo, 16u);
        CP_COMMIT();
    };

    auto compute = [&](int k) {
        uint32_t bs = sb + (uint32_t)(k % NSTG) * ST_SZ;
        #pragma unroll
        for (int ks = 0; ks < 2; ks++) {
            uint32_t cA = (((uint32_t)(ks * 2 + hi)) ^ swA) << 4;
            uint32_t af[4][4];
            #pragma unroll
            for (int mi = 0; mi < 4; mi++)
                ldsm_x4(af[mi][0], af[mi][1], af[mi][2], af[mi][3],
                        bs + aRow + (uint32_t)(mi * 1024) + cA);
            uint32_t bg[2][2], bu[2][2];
            uint32_t bt = bs + bRow + (uint32_t)(ks * 2048) + cB;
            ldsm_x4t(bg[0][0], bg[0][1], bg[1][0], bg[1][1], bt);
            ldsm_x4t(bu[0][0], bu[0][1], bu[1][0], bu[1][1], bt + 4096);
            #pragma unroll
            for (int mi = 0; mi < 4; mi++) {
                #pragma unroll
                for (int ni = 0; ni < 2; ni++) {
                    mma_f16(cg[mi][ni], af[mi], bg[ni]);
                    mma_f16(cu[mi][ni], af[mi], bu[ni]);
                }
            }
        }
    };

    issue(0); issue(1); issue(2); issue(3);
    const int KIT = DIM / BK;  // 32
    for (int j = 0; j < KIT / 2; j++) {
        int k0 = 2 * j;
        CP_WAIT2();
        __syncthreads();
        compute(k0);
        compute(k0 + 1);
        if (k0 + 4 < KIT) issue(k0 + 4); else CP_COMMIT();
        if (k0 + 5 < KIT) issue(k0 + 5); else CP_COMMIT();
    }

    #pragma unroll
    for (int mi = 0; mi < 4; mi++) {
        #pragma unroll
        for (int ni = 0; ni < 2; ni++) {
            int rbase = m0 + wm * 64 + mi * 16 + (lane >> 2);
            int cbase = n0 + wn * 16 + ni * 8 + (lane & 3) * 2;
            #pragma unroll
            for (int h = 0; h < 2; h++) {
                int row = rbase + h * 8;
                if (row < cnt) {
                    float g0 = cg[mi][ni][h * 2 + 0], g1 = cg[mi][ni][h * 2 + 1];
                    float u0 = cu[mi][ni][h * 2 + 0], u1 = cu[mi][ni][h * 2 + 1];
                    float h0 = g0 / (1.f + __expf(-g0)) * u0;
                    float h1 = g1 / (1.f + __expf(-g1)) * u1;
                    *(__half2*)(H + (size_t)row * FDIM + cbase) = __floats2half2_rn(h0, h1);
                }
            }
        }
    }
}

// ---------------- stage 2: Y = H @ down, BN=128 ------------------------------
__global__ void __launch_bounds__(256, 2) ffn2_h(
    const __half* __restrict__ dw_base,
    int mode)
{
    int e   = blockIdx.z;
    int cnt = mode ? T_TOK : g_cnt[e];
    int m0  = blockIdx.x * BM;
    if (m0 >= cnt) return;
    int n0  = blockIdx.y * 128;

    const __half* A  = mode ? g_Hs : (g_H + (size_t)e * T_TOK * FDIM);
    const __half* dwe = dw_base + (size_t)e * FDIM * DIM;
    float* Y = mode ? g_Ys : (g_Yr + (size_t)e * T_TOK * DIM);

    extern __shared__ char smem[];
    uint32_t sb = smem_u32(smem);
    int tid  = threadIdx.x;
    int lane = tid & 31, wid = tid >> 5;
    int wm = wid & 1, wn = wid >> 1;   // warp tile 64x32

    const char* aSrc[2]; uint32_t aZ[2], aDst[2];
    const char* bSrc[2]; uint32_t bDst[2];
    #pragma unroll
    for (int j = 0; j < 2; j++) {
        int idx = tid + j * 256;
        int row = idx >> 2, seg = idx & 3;
        aDst[j] = (uint32_t)(row * 64 + ((seg ^ ((row >> 1) & 3)) << 4));
        int grow = m0 + row;
        bool v = grow < cnt;
        aSrc[j] = (const char*)(A + (size_t)(v ? grow : 0) * FDIM + seg * 8);
        aZ[j] = v ? 16u : 0u;
        int br = idx >> 4, bsg = idx & 15;   // B: 32 rows x 256B
        bDst[j] = (uint32_t)(A_SZ + br * 256 + ((bsg ^ (br & 7)) << 4));
        bSrc[j] = (const char*)(dwe + (size_t)br * DIM + n0 + bsg * 8);
    }

    int hi = lane >> 4, lrow = lane & 15;
    uint32_t aRow = (uint32_t)((wm * 64 + lrow) * 64);
    uint32_t swA  = (uint32_t)((lrow >> 1) & 3);
    uint32_t bRow = (uint32_t)(A_SZ + lrow * 256);
    uint32_t swB  = (uint32_t)(lrow & 7);
    uint32_t cB1  = ((uint32_t)(wn * 4 + hi)     ^ swB) << 4;
    uint32_t cB2  = ((uint32_t)(wn * 4 + hi + 2) ^ swB) << 4;

    float cc_[4][4][4] = {};

    auto issue = [&](int k) {
        uint32_t base = sb + (uint32_t)(k % NSTG) * ST_SZ;
        size_t ao = (size_t)k * 64;
        size_t bo = (size_t)k * (BK * DIM * 2);
        cpa16(base + aDst[0], aSrc[0] + ao, aZ[0]);
        cpa16(base + aDst[1], aSrc[1] + ao, aZ[1]);
        cpa16(base + bDst[0], bSrc[0] + bo, 16u);
        cpa16(base + bDst[1], bSrc[1] + bo, 16u);
        CP_COMMIT();
    };

    auto compute = [&](int k) {
        uint32_t bs = sb + (uint32_t)(k % NSTG) * ST_SZ;
        #pragma unroll
        for (int ks = 0; ks < 2; ks++) {
            uint32_t cA = (((uint32_t)(ks * 2 + hi)) ^ swA) << 4;
            uint32_t af[4][4];
            #pragma unroll
            for (int mi = 0; mi < 4; mi++)
                ldsm_x4(af[mi][0], af[mi][1], af[mi][2], af[mi][3],
                        bs + aRow + (uint32_t)(mi * 1024) + cA);
            uint32_t bf[4][2];
            uint32_t bt = bs + bRow + (uint32_t)(ks * 4096);
            ldsm_x4t(bf[0][0], bf[0][1], bf[1][0], bf[1][1], bt + cB1);
            ldsm_x4t(bf[2][0], bf[2][1], bf[3][0], bf[3][1], bt + cB2);
            #pragma unroll
            for (int mi = 0; mi < 4; mi++)
                #pragma unroll
                for (int ni = 0; ni < 4; ni++)
                    mma_f16(cc_[mi][ni], af[mi], bf[ni]);
        }
    };

    issue(0); issue(1); issue(2); issue(3);
    const int KIT = FDIM / BK;  // 86
    for (int j = 0; j < KIT / 2; j++) {
        int k0 = 2 * j;
        CP_WAIT2();
        __syncthreads();
        compute(k0);
        compute(k0 + 1);
        if (k0 + 4 < KIT) issue(k0 + 4); else CP_COMMIT();
        if (k0 + 5 < KIT) issue(k0 + 5); else CP_COMMIT();
    }

    #pragma unroll
    for (int mi = 0; mi < 4; mi++) {
        #pragma unroll
        for (int ni = 0; ni < 4; ni++) {
            int rbase = m0 + wm * 64 + mi * 16 + (lane >> 2);
            int cbase = n0 + wn * 32 + ni * 8 + (lane & 3) * 2;
            #pragma unroll
            for (int h = 0; h < 2; h++) {
                int row = rbase + h * 8;
                if (row < cnt) {
                    Y[(size_t)row * DIM + cbase]     = cc_[mi][ni][h * 2 + 0];
                    Y[(size_t)row * DIM + cbase + 1] = cc_[mi][ni][h * 2 + 1];
                }
            }
        }
    }
}

// ---------------- combine ----------------------------------------------------
__global__ void combine_kernel(float* __restrict__ out) {
    int i  = blockIdx.x * blockDim.x + threadIdx.x;
    int t  = i / (DIM / 4);
    int dv = (i % (DIM / 4)) * 4;
    float w0 = g_cw[2 * t], w1 = g_cw[2 * t + 1];
    size_t s0 = (size_t)g_slot[2 * t] * DIM + dv;
    size_t s1 = (size_t)g_slot[2 * t + 1] * DIM + dv;
    float4 a = *(const float4*)(g_Yr + s0);
    float4 b = *(const float4*)(g_Yr + s1);
    float4 c = *(const float4*)(g_Ys + (size_t)t * DIM + dv);
    float4 o;
    o.x = w0 * a.x + w1 * b.x + c.x;
    o.y = w0 * a.y + w1 * b.y + c.y;
    o.z = w0 * a.z + w1 * b.z + c.z;
    o.w = w0 * a.w + w1 * b.w + c.w;
    *(float4*)(out + (size_t)t * DIM + dv) = o;
}

// ---------------- launch ------------------------------------------------------
extern "C" void kernel_launch(void* const* d_in, const int* in_sizes, int n_in,
                              void* d_out, int out_size) {
    const float* x   = (const float*)d_in[0];
    const float* rw  = (const float*)d_in[1];
    const float* rb  = (const float*)d_in[2];
    const float* gw  = (const float*)d_in[3];
    const float* uw  = (const float*)d_in[4];
    const float* dw  = (const float*)d_in[5];
    const float* sgw = (const float*)d_in[6];
    const float* suw = (const float*)d_in[7];
    const float* sdw = (const float*)d_in[8];
    float* out = (float*)d_out;

    cudaFuncSetAttribute(ffn1_h, cudaFuncAttributeMaxDynamicSharedMemorySize, SMEM_SZ);
    cudaFuncSetAttribute(ffn2_h, cudaFuncAttributeMaxDynamicSharedMemorySize, SMEM_SZ);

    __half *xh, *gwH, *uwH, *dwH, *sgwH, *suwH, *sdwH;
    cudaGetSymbolAddress((void**)&xh,   g_xH);
    cudaGetSymbolAddress((void**)&gwH,  g_gwH);
    cudaGetSymbolAddress((void**)&uwH,  g_uwH);
    cudaGetSymbolAddress((void**)&dwH,  g_dwH);
    cudaGetSymbolAddress((void**)&sgwH, g_sgwH);
    cudaGetSymbolAddress((void**)&suwH, g_suwH);
    cudaGetSymbolAddress((void**)&sdwH, g_sdwH);

    const size_t WQ  = (size_t)NEXP * DIM * FDIM / 4;
    const size_t SWQ = (size_t)DIM * FDIM / 4;

    cvtx_zero_kernel<<<(T_TOK * DIM) / 1024, 256>>>(x, xh);                       // 1
    router_kernel<<<T_TOK / 8, 256>>>(x, rw, rb);                                 // 2
    cvt2_kernel<<<(int)(2 * WQ / 256), 256>>>(gw, uw, gwH, uwH, WQ);              // 3
    dim3 g1(T_TOK / BM, FDIM / 64, NEXP);
    ffn1_h<<<g1, 256, SMEM_SZ>>>(xh, gwH, uwH, 0);                                // 4 <- profiled
    cvt2_kernel<<<(int)(2 * SWQ / 256), 256>>>(sgw, suw, sgwH, suwH, SWQ);        // 5
    dim3 g1s(T_TOK / BM, FDIM / 64, 1);
    ffn1_h<<<g1s, 256, SMEM_SZ>>>(xh, sgwH, suwH, 1);                             // 6
    cvt2_kernel<<<(int)(2 * (WQ / 2) / 256), 256>>>(dw, dw + WQ * 2, dwH,
                                                    dwH + WQ * 2, WQ / 2);        // 7
    dim3 g2(T_TOK / BM, DIM / 128, NEXP);
    ffn2_h<<<g2, 256, SMEM_SZ>>>(dwH, 0);                                         // 8
    cvt2_kernel<<<(int)(2 * (SWQ / 2) / 256), 256>>>(sdw, sdw + SWQ * 2, sdwH,
                                                     sdwH + SWQ * 2, SWQ / 2);    // 9
    dim3 g2s(T_TOK / BM, DIM / 128, 1);
    ffn2_h<<<g2s, 256, SMEM_SZ>>>(sdwH, 1);                                       // 10
    combine_kernel<<<(T_TOK * (DIM / 4)) / 256, 256>>>(out);                      // 11
}